// round 7
// baseline (speedup 1.0000x reference)
#include <cuda_runtime.h>
#include <cuda_bf16.h>
#include <cstdint>

// Problem constants
#define HW     262144        // 512*512
#define NB_B   2
#define NCH    48
#define NC3    144
#define NHEADS 8

// Scratch (device globals: no allocation allowed)
__device__ float g_qkv[NB_B * NC3 * HW];     // after 1x1 qkv conv
__device__ float g_dw[NB_B * NC3 * HW];      // after depthwise 3x3
__device__ float g_ao[NB_B * NCH * HW];      // after attn@V (from_blocks layout)
__device__ float g_norm2[NB_B * 96 * 16];    // per (b, q/k-ch, y%4, x%4) sum sq
__device__ float g_S[NB_B * NHEADS * 96 * 96]; // gram -> softmaxed attn

typedef unsigned long long u64;

__device__ __forceinline__ void fma2(u64& d, u64 a, u64 b) {
    asm("fma.rn.f32x2 %0, %1, %2, %0;" : "+l"(d) : "l"(a), "l"(b));
}
__device__ __forceinline__ u64 pk2(float lo, float hi) {
    u64 r; asm("mov.b64 %0, {%1, %2};" : "=l"(r) : "f"(lo), "f"(hi)); return r;
}
__device__ __forceinline__ float hsum(u64 v) {
    float lo, hi; asm("mov.b64 {%0, %1}, %2;" : "=f"(lo), "=f"(hi) : "l"(v)); return lo + hi;
}
__device__ __forceinline__ void up2(u64 v, float& lo, float& hi) {
    asm("mov.b64 {%0, %1}, %2;" : "=f"(lo), "=f"(hi) : "l"(v));
}

// bf16 warp MMA: D[16x8] += A[16x16] * B^T (B row-major [8 n][16 k])
__device__ __forceinline__ void mma_bf16(float* d, const uint32_t* a,
                                         uint32_t b0, uint32_t b1) {
    asm volatile(
        "mma.sync.aligned.m16n8k16.row.col.f32.bf16.bf16.f32 "
        "{%0,%1,%2,%3}, {%4,%5,%6,%7}, {%8,%9}, {%0,%1,%2,%3};"
        : "+f"(d[0]), "+f"(d[1]), "+f"(d[2]), "+f"(d[3])
        : "r"(a[0]), "r"(a[1]), "r"(a[2]), "r"(a[3]), "r"(b0), "r"(b1));
}

extern __shared__ float dynsm[];

// ---------------------------------------------------------------------------
// K0: zero the accumulation buffers
// ---------------------------------------------------------------------------
__global__ void k_zero() {
    int i = blockIdx.x * 256 + threadIdx.x;
    if (i < NB_B * NHEADS * 96 * 96) g_S[i] = 0.f;
    if (i < NB_B * 96 * 16)          g_norm2[i] = 0.f;
}

// ---------------------------------------------------------------------------
// K1/K6: 1x1 conv via bf16 mma.sync, split-bf16 (hh + h*lo + lo*h)
// Block: D[128 px, NOUT] = X[128, 48] @ W[NOUT, 48]^T.  Warp: 16 px rows.
// smem row stride 28 b32 words (==-4 mod 32 -> conflict-free frag loads)
// ---------------------------------------------------------------------------
template<int NOUT>
__global__ void __launch_bounds__(256) k_c11_mma(const float* __restrict__ in,
                                                 const float* __restrict__ w,
                                                 float* __restrict__ out) {
    constexpr int NT = NOUT / 8;
    uint32_t* Ah32 = (uint32_t*)dynsm;                 // [128][28]
    uint32_t* Al32 = Ah32 + 128 * 28;
    uint32_t* Bh32 = Al32 + 128 * 28;                  // [NOUT][28]
    uint32_t* Bl32 = Bh32 + NOUT * 28;
    float*    stag = (float*)(Bl32 + NOUT * 28);       // [8 warps][16][9]
    __nv_bfloat16* Ah16 = (__nv_bfloat16*)Ah32;
    __nv_bfloat16* Al16 = (__nv_bfloat16*)Al32;
    __nv_bfloat16* Bh16 = (__nv_bfloat16*)Bh32;
    __nv_bfloat16* Bl16 = (__nv_bfloat16*)Bl32;

    int tid = threadIdx.x;
    int b = blockIdx.x >> 11;                 // 2048 tiles per batch
    int q = (blockIdx.x & 2047) * 128;
    const float* xb = in + b * (NCH * HW) + q;

    // fill A: [px][ic] hi/lo bf16 (1536 float4 loads, coalesced)
    for (int e = tid; e < 1536; e += 256) {
        int ch = e >> 5, c = e & 31;
        float4 f = *(const float4*)(xb + ch * HW + 4 * c);
        float vv[4] = {f.x, f.y, f.z, f.w};
#pragma unroll
        for (int j = 0; j < 4; j++) {
            int px = 4 * c + j;
            __nv_bfloat16 hi = __float2bfloat16(vv[j]);
            __nv_bfloat16 lo = __float2bfloat16(vv[j] - __bfloat162float(hi));
            Ah16[px * 56 + ch] = hi;
            Al16[px * 56 + ch] = lo;
        }
    }
    // fill B: [oc][ic] hi/lo
    for (int e = tid; e < NOUT * 48; e += 256) {
        int oc = e / 48, ic = e - oc * 48;
        float v = w[e];
        __nv_bfloat16 hi = __float2bfloat16(v);
        __nv_bfloat16 lo = __float2bfloat16(v - __bfloat162float(hi));
        Bh16[oc * 56 + ic] = hi;
        Bl16[oc * 56 + ic] = lo;
    }
    __syncthreads();

    int wid = tid >> 5, lane = tid & 31;
    int gr = lane >> 2, lp = lane & 3;
    int wpx = wid * 16;

    // A fragments in registers (3 ksteps, reused for every n-tile and pass)
    uint32_t ah[3][4], al[3][4];
#pragma unroll
    for (int ks = 0; ks < 3; ks++) {
        int r0 = (wpx + gr) * 28 + ks * 8 + lp;
        int r1 = (wpx + gr + 8) * 28 + ks * 8 + lp;
        ah[ks][0] = Ah32[r0];     ah[ks][1] = Ah32[r1];
        ah[ks][2] = Ah32[r0 + 4]; ah[ks][3] = Ah32[r1 + 4];
        al[ks][0] = Al32[r0];     al[ks][1] = Al32[r1];
        al[ks][2] = Al32[r0 + 4]; al[ks][3] = Al32[r1 + 4];
    }

    float* sg = stag + wid * 144;
    float* ob = out + b * (NOUT * HW) + q + wpx;

#pragma unroll
    for (int np = 0; np < NT / 2; np++) {
        float d[2][4] = {{0.f, 0.f, 0.f, 0.f}, {0.f, 0.f, 0.f, 0.f}};
#pragma unroll
        for (int ks = 0; ks < 3; ks++) {
#pragma unroll
            for (int t = 0; t < 2; t++) {
                int brow = ((2 * np + t) * 8 + gr) * 28 + ks * 8 + lp;
                uint32_t bh0 = Bh32[brow], bh1 = Bh32[brow + 4];
                uint32_t bl0 = Bl32[brow], bl1 = Bl32[brow + 4];
                mma_bf16(d[t], ah[ks], bh0, bh1);
                mma_bf16(d[t], ah[ks], bl0, bl1);
                mma_bf16(d[t], al[ks], bh0, bh1);
            }
        }
#pragma unroll
        for (int t = 0; t < 2; t++) {
            int nn = 2 * np + t;
            sg[gr * 9 + 2 * lp]           = d[t][0];
            sg[gr * 9 + 2 * lp + 1]       = d[t][1];
            sg[(gr + 8) * 9 + 2 * lp]     = d[t][2];
            sg[(gr + 8) * 9 + 2 * lp + 1] = d[t][3];
            __syncwarp();
#pragma unroll
            for (int i = 0; i < 4; i++) {
                int e = i * 32 + lane;
                int oc8 = e >> 4, pxr = e & 15;
                ob[(nn * 8 + oc8) * HW + pxr] = sg[pxr * 9 + oc8];
            }
            __syncwarp();
        }
    }
}

// ---------------------------------------------------------------------------
// K2: depthwise 3x3 (zero pad) + fused q/k squared-norm accumulation
// ---------------------------------------------------------------------------
__global__ void __launch_bounds__(128) k_dw(const float* __restrict__ dww) {
    int ch = blockIdx.z % NC3;
    int b  = blockIdx.z / NC3;
    __shared__ float wk[9];
    __shared__ float sb[16];
    int tid = threadIdx.y * 16 + threadIdx.x;
    if (tid < 9)  wk[tid] = dww[ch * 9 + tid];
    if (tid < 16) sb[tid] = 0.f;
    __syncthreads();

    int x0 = (blockIdx.x * 16 + threadIdx.x) * 4;
    int y0 = blockIdx.y * 8 + threadIdx.y;
    const float* in = g_qkv + (b * NC3 + ch) * HW;

    float v[3][6];
#pragma unroll
    for (int r = 0; r < 3; r++) {
        int y = y0 + r - 1;
        if (y >= 0 && y < 512) {
            const float* rp = in + y * 512;
            float4 m = *(const float4*)(rp + x0);
            v[r][0] = (x0 > 0) ? rp[x0 - 1] : 0.f;
            v[r][1] = m.x; v[r][2] = m.y; v[r][3] = m.z; v[r][4] = m.w;
            v[r][5] = (x0 + 4 < 512) ? rp[x0 + 4] : 0.f;
        } else {
#pragma unroll
            for (int c = 0; c < 6; c++) v[r][c] = 0.f;
        }
    }

    float o[4];
#pragma unroll
    for (int px = 0; px < 4; px++) {
        float s = 0.f;
#pragma unroll
        for (int r = 0; r < 3; r++)
#pragma unroll
            for (int c = 0; c < 3; c++)
                s += wk[r * 3 + c] * v[r][px + c];
        o[px] = s;
    }
    float4 ov = make_float4(o[0], o[1], o[2], o[3]);
    *(float4*)(g_dw + (b * NC3 + ch) * HW + y0 * 512 + x0) = ov;

    if (ch < 96) {
#pragma unroll
        for (int px = 0; px < 4; px++) {
            float s = o[px] * o[px];
            s += __shfl_xor_sync(0xffffffffu, s, 8);
            s += __shfl_xor_sync(0xffffffffu, s, 4);
            s += __shfl_xor_sync(0xffffffffu, s, 2);
            s += __shfl_xor_sync(0xffffffffu, s, 1);
            if ((tid & 15) == 0) atomicAdd(&sb[(y0 & 3) * 4 + px], s);
        }
        __syncthreads();
        if (tid < 16) atomicAdd(&g_norm2[(b * 96 + ch) * 16 + tid], sb[tid]);
    }
}

// ---------------------------------------------------------------------------
// K3: raw gram [R1 version: scalar fills, register prefetch, 2 blocks/SM]
// ---------------------------------------------------------------------------
__global__ void __launch_bounds__(256, 2) k_gram() {
    int bh = blockIdx.y;
    int b = bh >> 3, h = bh & 7;
    int chunk = blockIdx.x;                  // 256 columns per chunk, 16 steps
    __shared__ __align__(16) float qs[96 * 18];
    __shared__ __align__(16) float ks[96 * 18];
    int tid = threadIdx.x;
    int ty = tid >> 4, tx = tid & 15;
    int kk = tid & 15;

    const float* qb = g_dw + (b * NC3 + h * 6) * HW;
    const float* kb = qb + 48 * HW;

    int offs[6];
#pragma unroll
    for (int u = 0; u < 6; u++) {
        int row = u * 16 + ty;
        int cc = row >> 4, nh = (row >> 2) & 3, nw = row & 3;
        offs[u] = cc * HW + nh * 512 + nw + 4 * kk;
    }

    u64 A[36];
#pragma unroll
    for (int e = 0; e < 36; e++) A[e] = 0;

    float rq[6], rk[6];
    {
        int so = (2 * chunk) * 2048;         // step 0
#pragma unroll
        for (int u = 0; u < 6; u++) {
            rq[u] = qb[offs[u] + so];
            rk[u] = kb[offs[u] + so];
        }
    }

    for (int s = 0; s < 16; s++) {
#pragma unroll
        for (int u = 0; u < 6; u++) {
            int sidx = (u * 16 + ty) * 18 + kk;
            qs[sidx] = rq[u];
            ks[sidx] = rk[u];
        }
        __syncthreads();
        if (s < 15) {
            int s1 = s + 1;
            int so1 = (2 * chunk + (s1 >> 3)) * 2048 + (s1 & 7) * 64;
#pragma unroll
            for (int u = 0; u < 6; u++) {
                rq[u] = qb[offs[u] + so1];
                rk[u] = kb[offs[u] + so1];
            }
        }
#pragma unroll
        for (int k2 = 0; k2 < 8; k2++) {
            u64 qv[6], kv[6];
#pragma unroll
            for (int a = 0; a < 6; a++)
                qv[a] = *(const u64*)&qs[(6 * ty + a) * 18 + 2 * k2];
#pragma unroll
            for (int d = 0; d < 6; d++)
                kv[d] = *(const u64*)&ks[(6 * tx + d) * 18 + 2 * k2];
#pragma unroll
            for (int a = 0; a < 6; a++)
#pragma unroll
                for (int d = 0; d < 6; d++)
                    fma2(A[a * 6 + d], qv[a], kv[d]);
        }
        __syncthreads();
    }

    float* Sp = g_S + bh * (96 * 96);
#pragma unroll
    for (int a = 0; a < 6; a++)
#pragma unroll
        for (int d = 0; d < 6; d++)
            atomicAdd(&Sp[(6 * ty + a) * 96 + (6 * tx + d)], hsum(A[a * 6 + d]));
}

// ---------------------------------------------------------------------------
// K4: fold norms + temperature, softmax rows (in-place in g_S)
// ---------------------------------------------------------------------------
__global__ void k_soft(const float* __restrict__ temp) {
    int bh = blockIdx.x;
    int b = bh >> 3, h = bh & 7;
    int r = threadIdx.x;                     // 0..95
    __shared__ float nk[96];

    float sq = g_norm2[(b * 96 + h * 6 + (r >> 4)) * 16 + (r & 15)];
    float nq = fmaxf(sqrtf(sq), 1e-12f);
    float sk = g_norm2[(b * 96 + 48 + h * 6 + (r >> 4)) * 16 + (r & 15)];
    nk[r] = fmaxf(sqrtf(sk), 1e-12f);
    __syncthreads();

    float t = temp[h];
    float* row = g_S + (bh * 96 + r) * 96;
    float vals[96];
    float m = -1e30f;
#pragma unroll
    for (int d = 0; d < 96; d++) {
        float a = row[d] / (nq * nk[d]) * t;
        vals[d] = a;
        m = fmaxf(m, a);
    }
    float ssum = 0.f;
#pragma unroll
    for (int d = 0; d < 96; d++) {
        float e = expf(vals[d] - m);
        vals[d] = e;
        ssum += e;
    }
    float inv = 1.f / ssum;
#pragma unroll
    for (int d = 0; d < 96; d++) row[d] = vals[d] * inv;
}

// ---------------------------------------------------------------------------
// K5: out = attn @ v, from_blocks layout; 6 rows x 4 cols/thread
// ---------------------------------------------------------------------------
__global__ void __launch_bounds__(256) k_av() {
    int bh = blockIdx.y;
    int b = bh >> 3, h = bh & 7;
    int tid = threadIdx.x;
    int ty = tid >> 4, tx = tid & 15;

    float* atT = dynsm;                  // 96*97 floats
    float* vs  = dynsm + 96 * 97;        // 96*64 floats

    const float* Sp = g_S + bh * 9216;
    for (int e = tid; e < 9216; e += 256) {
        int r = e / 96;
        int d = e - r * 96;
        atT[d * 97 + r] = Sp[e];
    }

    int n0 = blockIdx.x * 64;
    int i  = n0 >> 7;
    int j0 = n0 & 127;
    const float* vb = g_dw + (b * NC3 + 96 + h * 6) * HW;
    for (int e = tid; e < 1536; e += 256) {
        int rg = e >> 6, c = e & 63;
        int dc = rg >> 2, dh = rg & 3;
        float4 f = *(const float4*)(vb + dc * HW + (4 * i + dh) * 512 + 4 * (j0 + c));
        vs[(4 * rg + 0) * 64 + c] = f.x;
        vs[(4 * rg + 1) * 64 + c] = f.y;
        vs[(4 * rg + 2) * 64 + c] = f.z;
        vs[(4 * rg + 3) * 64 + c] = f.w;
    }
    __syncthreads();

    u64 A[12];
#pragma unroll
    for (int e = 0; e < 12; e++) A[e] = 0;

#pragma unroll 4
    for (int kd = 0; kd < 96; kd++) {
        float a[6];
#pragma unroll
        for (int u = 0; u < 6; u++) a[u] = atT[kd * 97 + 6 * ty + u];
        ulonglong2 v2 = *(const ulonglong2*)&vs[kd * 64 + 4 * tx];
#pragma unroll
        for (int u = 0; u < 6; u++) {
            u64 asp = pk2(a[u], a[u]);
            fma2(A[u * 2 + 0], asp, v2.x);
            fma2(A[u * 2 + 1], asp, v2.y);
        }
    }

    float* ob = g_ao + (b * NCH + h * 6) * HW;
#pragma unroll
    for (int u = 0; u < 6; u++) {
        int r = 6 * ty + u;
        int cc = r >> 4, nh = (r >> 2) & 3, nw = r & 3;
        int base = cc * HW + (4 * i + nh) * 512 + nw;
        float c0, c1, c2, c3;
        up2(A[u * 2 + 0], c0, c1);
        up2(A[u * 2 + 1], c2, c3);
        int j = j0 + 4 * tx;
        ob[base + 4 * (j + 0)] = c0;
        ob[base + 4 * (j + 1)] = c1;
        ob[base + 4 * (j + 2)] = c2;
        ob[base + 4 * (j + 3)] = c3;
    }
}

// ---------------------------------------------------------------------------
extern "C" void kernel_launch(void* const* d_in, const int* in_sizes, int n_in,
                              void* d_out, int out_size) {
    const float* x     = (const float*)d_in[0];
    const float* qkvw  = (const float*)d_in[1];
    const float* dww   = (const float*)d_in[2];
    const float* projw = (const float*)d_in[3];
    const float* temp  = (const float*)d_in[4];
    float* out = (float*)d_out;

    const int smem_qkv  = (128 * 28 * 2 + 144 * 28 * 2) * 4 + 8 * 144 * 4; // 65536
    const int smem_proj = (128 * 28 * 2 + 48 * 28 * 2) * 4 + 8 * 144 * 4;  // 44032
    cudaFuncSetAttribute(k_c11_mma<144>, cudaFuncAttributeMaxDynamicSharedMemorySize, smem_qkv);
    cudaFuncSetAttribute(k_c11_mma<48>,  cudaFuncAttributeMaxDynamicSharedMemorySize, smem_proj);
    cudaFuncSetAttribute(k_av, cudaFuncAttributeMaxDynamicSharedMemorySize,
                         (96 * 97 + 96 * 64) * 4);

    float* gqkv;  cudaGetSymbolAddress((void**)&gqkv, g_qkv);
    float* gao;   cudaGetSymbolAddress((void**)&gao,  g_ao);

    k_zero<<<576, 256>>>();
    k_c11_mma<144><<<4096, 256, smem_qkv>>>(x, qkvw, gqkv);
    k_dw<<<dim3(8, 64, NB_B * NC3), dim3(16, 8)>>>(dww);
    k_gram<<<dim3(64, NB_B * NHEADS), 256>>>();
    k_soft<<<NB_B * NHEADS, 96>>>(temp);
    k_av<<<dim3(256, NB_B * NHEADS), 256, (96 * 97 + 96 * 64) * 4>>>();
    k_c11_mma<48><<<4096, 256, smem_proj>>>(gao, projw, out);
}

// round 8
// speedup vs baseline: 1.1648x; 1.1648x over previous
#include <cuda_runtime.h>
#include <cuda_bf16.h>
#include <cstdint>

// Problem constants
#define HW     262144        // 512*512
#define NB_B   2
#define NCH    48
#define NC3    144
#define NHEADS 8

// Scratch (device globals: no allocation allowed)
__device__ float g_qkv[NB_B * NC3 * HW];     // after 1x1 qkv conv
__device__ float g_dw[NB_B * NC3 * HW];      // after depthwise 3x3
__device__ float g_ao[NB_B * NCH * HW];      // after attn@V (from_blocks layout)
__device__ float g_norm2[NB_B * 96 * 16];    // per (b, q/k-ch, y%4, x%4) sum sq
__device__ float g_S[NB_B * NHEADS * 96 * 96]; // gram -> softmaxed attn

typedef unsigned long long u64;

__device__ __forceinline__ void fma2(u64& d, u64 a, u64 b) {
    asm("fma.rn.f32x2 %0, %1, %2, %0;" : "+l"(d) : "l"(a), "l"(b));
}
__device__ __forceinline__ u64 pk2(float lo, float hi) {
    u64 r; asm("mov.b64 %0, {%1, %2};" : "=l"(r) : "f"(lo), "f"(hi)); return r;
}
__device__ __forceinline__ float hsum(u64 v) {
    float lo, hi; asm("mov.b64 {%0, %1}, %2;" : "=f"(lo), "=f"(hi) : "l"(v)); return lo + hi;
}
__device__ __forceinline__ void up2(u64 v, float& lo, float& hi) {
    asm("mov.b64 {%0, %1}, %2;" : "=f"(lo), "=f"(hi) : "l"(v));
}

// bf16 warp MMA: D[16x8] += A[16x16] row-major * B[8n x 16k] row-major
__device__ __forceinline__ void mma_bf16(float* d, const uint32_t* a,
                                         uint32_t b0, uint32_t b1) {
    asm volatile(
        "mma.sync.aligned.m16n8k16.row.col.f32.bf16.bf16.f32 "
        "{%0,%1,%2,%3}, {%4,%5,%6,%7}, {%8,%9}, {%0,%1,%2,%3};"
        : "+f"(d[0]), "+f"(d[1]), "+f"(d[2]), "+f"(d[3])
        : "r"(a[0]), "r"(a[1]), "r"(a[2]), "r"(a[3]), "r"(b0), "r"(b1));
}

// split v0,v1 into bf16 hi/lo pairs packed as u32 (low half = v0)
__device__ __forceinline__ void split2(float v0, float v1,
                                       uint32_t& hi, uint32_t& lo) {
    __nv_bfloat162 h = __floats2bfloat162_rn(v0, v1);
    float r0 = v0 - __bfloat162float(h.x);
    float r1 = v1 - __bfloat162float(h.y);
    __nv_bfloat162 l = __floats2bfloat162_rn(r0, r1);
    hi = *(uint32_t*)&h;
    lo = *(uint32_t*)&l;
}

extern __shared__ float dynsm[];

// ---------------------------------------------------------------------------
// K0: zero the accumulation buffers
// ---------------------------------------------------------------------------
__global__ void k_zero() {
    int i = blockIdx.x * 256 + threadIdx.x;
    if (i < NB_B * NHEADS * 96 * 96) g_S[i] = 0.f;
    if (i < NB_B * 96 * 16)          g_norm2[i] = 0.f;
}

// ---------------------------------------------------------------------------
// K1: 1x1 conv 48 -> 144 as tiled GEMM [R5 f32x2 version]
// ---------------------------------------------------------------------------
__global__ void __launch_bounds__(256, 2) k_qkv(const float* __restrict__ x,
                                                const float* __restrict__ w) {
    float* Ws = dynsm;                 // 144*48 = 6912 floats
    float* Xs = dynsm + 6912;          // 48*128 = 6144 floats
    int tid = threadIdx.x;
    int ty = tid >> 4, tx = tid & 15;

    int b = blockIdx.x >> 11;
    int q = (blockIdx.x & 2047) * 128;
    const float* xb = x + b * (NCH * HW) + q;

    for (int e = tid * 4; e < 6912; e += 1024)
        *(float4*)&Ws[e] = *(const float4*)&w[e];
    for (int e = tid; e < 1536; e += 256) {
        int ch = e >> 5, c = e & 31;
        *(float4*)&Xs[ch * 128 + 4 * c] = *(const float4*)&xb[ch * HW + 4 * c];
    }
    __syncthreads();

    u64 acc[9][4];
#pragma unroll
    for (int j = 0; j < 9; j++)
#pragma unroll
        for (int i = 0; i < 4; i++) acc[j][i] = 0;

#pragma unroll 4
    for (int k = 0; k < 48; k++) {
        ulonglong2 xa = *(const ulonglong2*)&Xs[k * 128 + 8 * tx];
        ulonglong2 xc = *(const ulonglong2*)&Xs[k * 128 + 8 * tx + 4];
#pragma unroll
        for (int j = 0; j < 9; j++) {
            float wf = Ws[(9 * ty + j) * 48 + k];
            u64 wp = pk2(wf, wf);
            fma2(acc[j][0], wp, xa.x);
            fma2(acc[j][1], wp, xa.y);
            fma2(acc[j][2], wp, xc.x);
            fma2(acc[j][3], wp, xc.y);
        }
    }

    float* op = g_qkv + b * (NC3 * HW) + q + 8 * tx;
#pragma unroll
    for (int j = 0; j < 9; j++) {
        int oc = 9 * ty + j;
        float f0, f1, f2, f3, f4, f5, f6, f7;
        up2(acc[j][0], f0, f1);
        up2(acc[j][1], f2, f3);
        up2(acc[j][2], f4, f5);
        up2(acc[j][3], f6, f7);
        *(float4*)(op + oc * HW)     = make_float4(f0, f1, f2, f3);
        *(float4*)(op + oc * HW + 4) = make_float4(f4, f5, f6, f7);
    }
}

// ---------------------------------------------------------------------------
// K2: depthwise 3x3 (zero pad) + fused q/k squared-norm accumulation
// ---------------------------------------------------------------------------
__global__ void __launch_bounds__(128) k_dw(const float* __restrict__ dww) {
    int ch = blockIdx.z % NC3;
    int b  = blockIdx.z / NC3;
    __shared__ float wk[9];
    __shared__ float sb[16];
    int tid = threadIdx.y * 16 + threadIdx.x;
    if (tid < 9)  wk[tid] = dww[ch * 9 + tid];
    if (tid < 16) sb[tid] = 0.f;
    __syncthreads();

    int x0 = (blockIdx.x * 16 + threadIdx.x) * 4;
    int y0 = blockIdx.y * 8 + threadIdx.y;
    const float* in = g_qkv + (b * NC3 + ch) * HW;

    float v[3][6];
#pragma unroll
    for (int r = 0; r < 3; r++) {
        int y = y0 + r - 1;
        if (y >= 0 && y < 512) {
            const float* rp = in + y * 512;
            float4 m = *(const float4*)(rp + x0);
            v[r][0] = (x0 > 0) ? rp[x0 - 1] : 0.f;
            v[r][1] = m.x; v[r][2] = m.y; v[r][3] = m.z; v[r][4] = m.w;
            v[r][5] = (x0 + 4 < 512) ? rp[x0 + 4] : 0.f;
        } else {
#pragma unroll
            for (int c = 0; c < 6; c++) v[r][c] = 0.f;
        }
    }

    float o[4];
#pragma unroll
    for (int px = 0; px < 4; px++) {
        float s = 0.f;
#pragma unroll
        for (int r = 0; r < 3; r++)
#pragma unroll
            for (int c = 0; c < 3; c++)
                s += wk[r * 3 + c] * v[r][px + c];
        o[px] = s;
    }
    float4 ov = make_float4(o[0], o[1], o[2], o[3]);
    *(float4*)(g_dw + (b * NC3 + ch) * HW + y0 * 512 + x0) = ov;

    if (ch < 96) {
#pragma unroll
        for (int px = 0; px < 4; px++) {
            float s = o[px] * o[px];
            s += __shfl_xor_sync(0xffffffffu, s, 8);
            s += __shfl_xor_sync(0xffffffffu, s, 4);
            s += __shfl_xor_sync(0xffffffffu, s, 2);
            s += __shfl_xor_sync(0xffffffffu, s, 1);
            if ((tid & 15) == 0) atomicAdd(&sb[(y0 & 3) * 4 + px], s);
        }
        __syncthreads();
        if (tid < 16) atomicAdd(&g_norm2[(b * 96 + ch) * 16 + tid], sb[tid]);
    }
}

// ---------------------------------------------------------------------------
// K3: gram via mma.sync bf16 split (hh + h*lo + lo*h)
// grid (32 n-chunks of 512, 16 bh); 256 thr = 8 warps (2 m-groups x 4 n-groups)
// smem: Qhi/Qlo/Khi/Klo tiles [96 rows][72 bf16 stride] per 64-n sub-chunk
// ---------------------------------------------------------------------------
__global__ void __launch_bounds__(256, 2) k_gram_mma() {
    uint32_t* Qhi = (uint32_t*)dynsm;            // [96][36] u32
    uint32_t* Qlo = Qhi + 96 * 36;
    uint32_t* Khi = Qlo + 96 * 36;
    uint32_t* Klo = Khi + 96 * 36;

    int bh = blockIdx.y;
    int b = bh >> 3, h = bh & 7;
    int tid = threadIdx.x, wid = tid >> 5, lane = tid & 31;
    int gr = lane >> 2, lp = lane & 3;
    int mg = wid >> 2, ng = wid & 3;             // m base mg*48, n base ng*24

    const float* qb = g_dw + (b * NC3 + h * 6) * HW;
    const float* kb = qb + 48 * HW;

    float acc[3][3][4];
#pragma unroll
    for (int tm = 0; tm < 3; tm++)
#pragma unroll
        for (int tn = 0; tn < 3; tn++)
#pragma unroll
            for (int e = 0; e < 4; e++) acc[tm][tn][e] = 0.f;

    for (int sub = 0; sub < 8; sub++) {
        int n0 = blockIdx.x * 512 + sub * 64;
        int i = n0 >> 7, j0 = n0 & 127;

        // fill: each e covers (row-group rg, j-pair jp) -> 2 float4 q + 2 k
        for (int e = tid; e < 768; e += 256) {
            int rg = e >> 5, jp = e & 31;
            int cc = rg >> 2, nh = rg & 3;
            int off = cc * HW + (4 * i + nh) * 512 + 4 * (j0 + 2 * jp);
            float4 q0 = *(const float4*)(qb + off);
            float4 q1 = *(const float4*)(qb + off + 4);
            float4 k0 = *(const float4*)(kb + off);
            float4 k1 = *(const float4*)(kb + off + 4);
            int rb = rg * 4;
            uint32_t hi, lo;
            split2(q0.x, q1.x, hi, lo); Qhi[(rb+0)*36+jp] = hi; Qlo[(rb+0)*36+jp] = lo;
            split2(q0.y, q1.y, hi, lo); Qhi[(rb+1)*36+jp] = hi; Qlo[(rb+1)*36+jp] = lo;
            split2(q0.z, q1.z, hi, lo); Qhi[(rb+2)*36+jp] = hi; Qlo[(rb+2)*36+jp] = lo;
            split2(q0.w, q1.w, hi, lo); Qhi[(rb+3)*36+jp] = hi; Qlo[(rb+3)*36+jp] = lo;
            split2(k0.x, k1.x, hi, lo); Khi[(rb+0)*36+jp] = hi; Klo[(rb+0)*36+jp] = lo;
            split2(k0.y, k1.y, hi, lo); Khi[(rb+1)*36+jp] = hi; Klo[(rb+1)*36+jp] = lo;
            split2(k0.z, k1.z, hi, lo); Khi[(rb+2)*36+jp] = hi; Klo[(rb+2)*36+jp] = lo;
            split2(k0.w, k1.w, hi, lo); Khi[(rb+3)*36+jp] = hi; Klo[(rb+3)*36+jp] = lo;
        }
        __syncthreads();

#pragma unroll
        for (int kc = 0; kc < 4; kc++) {
            uint32_t ahi[3][4], alo[3][4], bhi[3][2], blo[3][2];
#pragma unroll
            for (int tm = 0; tm < 3; tm++) {
                int r0 = (mg * 48 + tm * 16 + gr) * 36 + kc * 8 + lp;
                int r1 = r0 + 8 * 36;
                ahi[tm][0] = Qhi[r0];     ahi[tm][1] = Qhi[r1];
                ahi[tm][2] = Qhi[r0 + 4]; ahi[tm][3] = Qhi[r1 + 4];
                alo[tm][0] = Qlo[r0];     alo[tm][1] = Qlo[r1];
                alo[tm][2] = Qlo[r0 + 4]; alo[tm][3] = Qlo[r1 + 4];
            }
#pragma unroll
            for (int tn = 0; tn < 3; tn++) {
                int rb = (ng * 24 + tn * 8 + gr) * 36 + kc * 8 + lp;
                bhi[tn][0] = Khi[rb]; bhi[tn][1] = Khi[rb + 4];
                blo[tn][0] = Klo[rb]; blo[tn][1] = Klo[rb + 4];
            }
#pragma unroll
            for (int tm = 0; tm < 3; tm++)
#pragma unroll
                for (int tn = 0; tn < 3; tn++) {
                    mma_bf16(acc[tm][tn], ahi[tm], bhi[tn][0], bhi[tn][1]);
                    mma_bf16(acc[tm][tn], ahi[tm], blo[tn][0], blo[tn][1]);
                    mma_bf16(acc[tm][tn], alo[tm], bhi[tn][0], bhi[tn][1]);
                }
        }
        __syncthreads();
    }

    float* Sp = g_S + bh * 9216;
#pragma unroll
    for (int tm = 0; tm < 3; tm++)
#pragma unroll
        for (int tn = 0; tn < 3; tn++) {
            int r0 = mg * 48 + tm * 16 + gr;
            int c0 = ng * 24 + tn * 8 + 2 * lp;
            atomicAdd(&Sp[r0 * 96 + c0],           acc[tm][tn][0]);
            atomicAdd(&Sp[r0 * 96 + c0 + 1],       acc[tm][tn][1]);
            atomicAdd(&Sp[(r0 + 8) * 96 + c0],     acc[tm][tn][2]);
            atomicAdd(&Sp[(r0 + 8) * 96 + c0 + 1], acc[tm][tn][3]);
        }
}

// ---------------------------------------------------------------------------
// K4: fold norms + temperature, softmax rows (in-place in g_S)
// ---------------------------------------------------------------------------
__global__ void k_soft(const float* __restrict__ temp) {
    int bh = blockIdx.x;
    int b = bh >> 3, h = bh & 7;
    int r = threadIdx.x;                     // 0..95
    __shared__ float nk[96];

    float sq = g_norm2[(b * 96 + h * 6 + (r >> 4)) * 16 + (r & 15)];
    float nq = fmaxf(sqrtf(sq), 1e-12f);
    float sk = g_norm2[(b * 96 + 48 + h * 6 + (r >> 4)) * 16 + (r & 15)];
    nk[r] = fmaxf(sqrtf(sk), 1e-12f);
    __syncthreads();

    float t = temp[h];
    float* row = g_S + (bh * 96 + r) * 96;
    float vals[96];
    float m = -1e30f;
#pragma unroll
    for (int d = 0; d < 96; d++) {
        float a = row[d] / (nq * nk[d]) * t;
        vals[d] = a;
        m = fmaxf(m, a);
    }
    float ssum = 0.f;
#pragma unroll
    for (int d = 0; d < 96; d++) {
        float e = expf(vals[d] - m);
        vals[d] = e;
        ssum += e;
    }
    float inv = 1.f / ssum;
#pragma unroll
    for (int d = 0; d < 96; d++) row[d] = vals[d] * inv;
}

// ---------------------------------------------------------------------------
// K5: out = attn @ v, from_blocks layout; 6 rows x 4 cols/thread
// ---------------------------------------------------------------------------
__global__ void __launch_bounds__(256) k_av() {
    int bh = blockIdx.y;
    int b = bh >> 3, h = bh & 7;
    int tid = threadIdx.x;
    int ty = tid >> 4, tx = tid & 15;

    float* atT = dynsm;                  // 96*97 floats
    float* vs  = dynsm + 96 * 97;        // 96*64 floats

    const float* Sp = g_S + bh * 9216;
    for (int e = tid; e < 9216; e += 256) {
        int r = e / 96;
        int d = e - r * 96;
        atT[d * 97 + r] = Sp[e];
    }

    int n0 = blockIdx.x * 64;
    int i  = n0 >> 7;
    int j0 = n0 & 127;
    const float* vb = g_dw + (b * NC3 + 96 + h * 6) * HW;
    for (int e = tid; e < 1536; e += 256) {
        int rg = e >> 6, c = e & 63;
        int dc = rg >> 2, dh = rg & 3;
        float4 f = *(const float4*)(vb + dc * HW + (4 * i + dh) * 512 + 4 * (j0 + c));
        vs[(4 * rg + 0) * 64 + c] = f.x;
        vs[(4 * rg + 1) * 64 + c] = f.y;
        vs[(4 * rg + 2) * 64 + c] = f.z;
        vs[(4 * rg + 3) * 64 + c] = f.w;
    }
    __syncthreads();

    u64 A[12];
#pragma unroll
    for (int e = 0; e < 12; e++) A[e] = 0;

#pragma unroll 4
    for (int kd = 0; kd < 96; kd++) {
        float a[6];
#pragma unroll
        for (int u = 0; u < 6; u++) a[u] = atT[kd * 97 + 6 * ty + u];
        ulonglong2 v2 = *(const ulonglong2*)&vs[kd * 64 + 4 * tx];
#pragma unroll
        for (int u = 0; u < 6; u++) {
            u64 asp = pk2(a[u], a[u]);
            fma2(A[u * 2 + 0], asp, v2.x);
            fma2(A[u * 2 + 1], asp, v2.y);
        }
    }

    float* ob = g_ao + (b * NCH + h * 6) * HW;
#pragma unroll
    for (int u = 0; u < 6; u++) {
        int r = 6 * ty + u;
        int cc = r >> 4, nh = (r >> 2) & 3, nw = r & 3;
        int base = cc * HW + (4 * i + nh) * 512 + nw;
        float c0, c1, c2, c3;
        up2(A[u * 2 + 0], c0, c1);
        up2(A[u * 2 + 1], c2, c3);
        int j = j0 + 4 * tx;
        ob[base + 4 * (j + 0)] = c0;
        ob[base + 4 * (j + 1)] = c1;
        ob[base + 4 * (j + 2)] = c2;
        ob[base + 4 * (j + 3)] = c3;
    }
}

// ---------------------------------------------------------------------------
// K6: 1x1 proj 48 -> 48 as tiled GEMM [R5 f32x2 version]
// ---------------------------------------------------------------------------
__global__ void __launch_bounds__(256, 2) k_proj(const float* __restrict__ w,
                                                 float* __restrict__ out) {
    __shared__ __align__(16) float Ws[NCH * NCH];     // 2304 floats
    __shared__ __align__(16) float Xs[NCH * 128];     // 6144 floats
    int tid = threadIdx.x;
    int ty = tid >> 4, tx = tid & 15;

    int b = blockIdx.x >> 11;
    int q = (blockIdx.x & 2047) * 128;
    const float* xb = g_ao + b * (NCH * HW) + q;

    for (int e = tid * 4; e < NCH * NCH; e += 1024)
        *(float4*)&Ws[e] = *(const float4*)&w[e];
    for (int e = tid; e < 1536; e += 256) {
        int ch = e >> 5, c = e & 31;
        *(float4*)&Xs[ch * 128 + 4 * c] = *(const float4*)&xb[ch * HW + 4 * c];
    }
    __syncthreads();

    u64 acc[3][4];
#pragma unroll
    for (int j = 0; j < 3; j++)
#pragma unroll
        for (int i = 0; i < 4; i++) acc[j][i] = 0;

#pragma unroll 4
    for (int k = 0; k < 48; k++) {
        ulonglong2 xa = *(const ulonglong2*)&Xs[k * 128 + 8 * tx];
        ulonglong2 xc = *(const ulonglong2*)&Xs[k * 128 + 8 * tx + 4];
#pragma unroll
        for (int j = 0; j < 3; j++) {
            float wf = Ws[(3 * ty + j) * 48 + k];
            u64 wp = pk2(wf, wf);
            fma2(acc[j][0], wp, xa.x);
            fma2(acc[j][1], wp, xa.y);
            fma2(acc[j][2], wp, xc.x);
            fma2(acc[j][3], wp, xc.y);
        }
    }

    float* op = out + b * (NCH * HW) + q + 8 * tx;
#pragma unroll
    for (int j = 0; j < 3; j++) {
        int oc = 3 * ty + j;
        float f0, f1, f2, f3, f4, f5, f6, f7;
        up2(acc[j][0], f0, f1);
        up2(acc[j][1], f2, f3);
        up2(acc[j][2], f4, f5);
        up2(acc[j][3], f6, f7);
        *(float4*)(op + oc * HW)     = make_float4(f0, f1, f2, f3);
        *(float4*)(op + oc * HW + 4) = make_float4(f4, f5, f6, f7);
    }
}

// ---------------------------------------------------------------------------
extern "C" void kernel_launch(void* const* d_in, const int* in_sizes, int n_in,
                              void* d_out, int out_size) {
    const float* x     = (const float*)d_in[0];
    const float* qkvw  = (const float*)d_in[1];
    const float* dww   = (const float*)d_in[2];
    const float* projw = (const float*)d_in[3];
    const float* temp  = (const float*)d_in[4];
    float* out = (float*)d_out;

    const int smem_gram = 4 * 96 * 36 * 4;   // 55296 bytes
    cudaFuncSetAttribute(k_qkv, cudaFuncAttributeMaxDynamicSharedMemorySize,
                         (6912 + 6144) * 4);
    cudaFuncSetAttribute(k_gram_mma, cudaFuncAttributeMaxDynamicSharedMemorySize,
                         smem_gram);
    cudaFuncSetAttribute(k_av, cudaFuncAttributeMaxDynamicSharedMemorySize,
                         (96 * 97 + 96 * 64) * 4);

    float* gqkv;  cudaGetSymbolAddress((void**)&gqkv, g_qkv);

    k_zero<<<576, 256>>>();
    k_qkv<<<4096, 256, (6912 + 6144) * 4>>>(x, qkvw);
    k_dw<<<dim3(8, 64, NB_B * NC3), dim3(16, 8)>>>(dww);
    k_gram_mma<<<dim3(32, NB_B * NHEADS), 256, smem_gram>>>();
    k_soft<<<NB_B * NHEADS, 96>>>(temp);
    k_av<<<dim3(256, NB_B * NHEADS), 256, (96 * 97 + 96 * 64) * 4>>>();
    k_proj<<<4096, 256>>>(projw, out);
}

// round 9
// speedup vs baseline: 1.3025x; 1.1183x over previous
#include <cuda_runtime.h>
#include <cuda_bf16.h>
#include <cstdint>

// Problem constants
#define HW     262144        // 512*512
#define NB_B   2
#define NCH    48
#define NC3    144
#define NHEADS 8

// Scratch (device globals: no allocation allowed)
__device__ float g_qkv[NB_B * NC3 * HW];     // after 1x1 qkv conv
__device__ float g_dw[NB_B * NC3 * HW];      // after depthwise 3x3
__device__ float g_ao[NB_B * NCH * HW];      // after attn@V (from_blocks layout)
__device__ float g_norm2[NB_B * 96 * 16];    // per (b, q/k-ch, y%4, x%4) sum sq
__device__ float g_S[NB_B * NHEADS * 96 * 96]; // gram -> softmaxed attn

typedef unsigned long long u64;

__device__ __forceinline__ void fma2(u64& d, u64 a, u64 b) {
    asm("fma.rn.f32x2 %0, %1, %2, %0;" : "+l"(d) : "l"(a), "l"(b));
}
__device__ __forceinline__ u64 pk2(float lo, float hi) {
    u64 r; asm("mov.b64 %0, {%1, %2};" : "=l"(r) : "f"(lo), "f"(hi)); return r;
}
__device__ __forceinline__ float hsum(u64 v) {
    float lo, hi; asm("mov.b64 {%0, %1}, %2;" : "=f"(lo), "=f"(hi) : "l"(v)); return lo + hi;
}
__device__ __forceinline__ void up2(u64 v, float& lo, float& hi) {
    asm("mov.b64 {%0, %1}, %2;" : "=f"(lo), "=f"(hi) : "l"(v));
}

// bf16 warp MMA: D[16x8] += A[16x16] row-major * B[8n x 16k] row-major
__device__ __forceinline__ void mma_bf16(float* d, const uint32_t* a,
                                         uint32_t b0, uint32_t b1) {
    asm volatile(
        "mma.sync.aligned.m16n8k16.row.col.f32.bf16.bf16.f32 "
        "{%0,%1,%2,%3}, {%4,%5,%6,%7}, {%8,%9}, {%0,%1,%2,%3};"
        : "+f"(d[0]), "+f"(d[1]), "+f"(d[2]), "+f"(d[3])
        : "r"(a[0]), "r"(a[1]), "r"(a[2]), "r"(a[3]), "r"(b0), "r"(b1));
}

// split v0,v1 into bf16 hi/lo pairs packed as u32 (low half = v0)
__device__ __forceinline__ void split2(float v0, float v1,
                                       uint32_t& hi, uint32_t& lo) {
    __nv_bfloat162 h = __floats2bfloat162_rn(v0, v1);
    float r0 = v0 - __bfloat162float(h.x);
    float r1 = v1 - __bfloat162float(h.y);
    __nv_bfloat162 l = __floats2bfloat162_rn(r0, r1);
    hi = *(uint32_t*)&h;
    lo = *(uint32_t*)&l;
}

extern __shared__ float dynsm[];

// ---------------------------------------------------------------------------
// K0: zero the accumulation buffers
// ---------------------------------------------------------------------------
__global__ void k_zero() {
    int i = blockIdx.x * 256 + threadIdx.x;
    if (i < NB_B * NHEADS * 96 * 96) g_S[i] = 0.f;
    if (i < NB_B * 96 * 16)          g_norm2[i] = 0.f;
}

// ---------------------------------------------------------------------------
// K1: 1x1 conv 48 -> 144 as tiled GEMM [R5 f32x2 version]
// ---------------------------------------------------------------------------
__global__ void __launch_bounds__(256, 2) k_qkv(const float* __restrict__ x,
                                                const float* __restrict__ w) {
    float* Ws = dynsm;                 // 144*48 = 6912 floats
    float* Xs = dynsm + 6912;          // 48*128 = 6144 floats
    int tid = threadIdx.x;
    int ty = tid >> 4, tx = tid & 15;

    int b = blockIdx.x >> 11;
    int q = (blockIdx.x & 2047) * 128;
    const float* xb = x + b * (NCH * HW) + q;

    for (int e = tid * 4; e < 6912; e += 1024)
        *(float4*)&Ws[e] = *(const float4*)&w[e];
    for (int e = tid; e < 1536; e += 256) {
        int ch = e >> 5, c = e & 31;
        *(float4*)&Xs[ch * 128 + 4 * c] = *(const float4*)&xb[ch * HW + 4 * c];
    }
    __syncthreads();

    u64 acc[9][4];
#pragma unroll
    for (int j = 0; j < 9; j++)
#pragma unroll
        for (int i = 0; i < 4; i++) acc[j][i] = 0;

#pragma unroll 4
    for (int k = 0; k < 48; k++) {
        ulonglong2 xa = *(const ulonglong2*)&Xs[k * 128 + 8 * tx];
        ulonglong2 xc = *(const ulonglong2*)&Xs[k * 128 + 8 * tx + 4];
#pragma unroll
        for (int j = 0; j < 9; j++) {
            float wf = Ws[(9 * ty + j) * 48 + k];
            u64 wp = pk2(wf, wf);
            fma2(acc[j][0], wp, xa.x);
            fma2(acc[j][1], wp, xa.y);
            fma2(acc[j][2], wp, xc.x);
            fma2(acc[j][3], wp, xc.y);
        }
    }

    float* op = g_qkv + b * (NC3 * HW) + q + 8 * tx;
#pragma unroll
    for (int j = 0; j < 9; j++) {
        int oc = 9 * ty + j;
        float f0, f1, f2, f3, f4, f5, f6, f7;
        up2(acc[j][0], f0, f1);
        up2(acc[j][1], f2, f3);
        up2(acc[j][2], f4, f5);
        up2(acc[j][3], f6, f7);
        *(float4*)(op + oc * HW)     = make_float4(f0, f1, f2, f3);
        *(float4*)(op + oc * HW + 4) = make_float4(f4, f5, f6, f7);
    }
}

// ---------------------------------------------------------------------------
// K2: depthwise 3x3 (zero pad) + fused q/k squared-norm accumulation
// ---------------------------------------------------------------------------
__global__ void __launch_bounds__(128) k_dw(const float* __restrict__ dww) {
    int ch = blockIdx.z % NC3;
    int b  = blockIdx.z / NC3;
    __shared__ float wk[9];
    __shared__ float sb[16];
    int tid = threadIdx.y * 16 + threadIdx.x;
    if (tid < 9)  wk[tid] = dww[ch * 9 + tid];
    if (tid < 16) sb[tid] = 0.f;
    __syncthreads();

    int x0 = (blockIdx.x * 16 + threadIdx.x) * 4;
    int y0 = blockIdx.y * 8 + threadIdx.y;
    const float* in = g_qkv + (b * NC3 + ch) * HW;

    float v[3][6];
#pragma unroll
    for (int r = 0; r < 3; r++) {
        int y = y0 + r - 1;
        if (y >= 0 && y < 512) {
            const float* rp = in + y * 512;
            float4 m = *(const float4*)(rp + x0);
            v[r][0] = (x0 > 0) ? rp[x0 - 1] : 0.f;
            v[r][1] = m.x; v[r][2] = m.y; v[r][3] = m.z; v[r][4] = m.w;
            v[r][5] = (x0 + 4 < 512) ? rp[x0 + 4] : 0.f;
        } else {
#pragma unroll
            for (int c = 0; c < 6; c++) v[r][c] = 0.f;
        }
    }

    float o[4];
#pragma unroll
    for (int px = 0; px < 4; px++) {
        float s = 0.f;
#pragma unroll
        for (int r = 0; r < 3; r++)
#pragma unroll
            for (int c = 0; c < 3; c++)
                s += wk[r * 3 + c] * v[r][px + c];
        o[px] = s;
    }
    float4 ov = make_float4(o[0], o[1], o[2], o[3]);
    *(float4*)(g_dw + (b * NC3 + ch) * HW + y0 * 512 + x0) = ov;

    if (ch < 96) {
#pragma unroll
        for (int px = 0; px < 4; px++) {
            float s = o[px] * o[px];
            s += __shfl_xor_sync(0xffffffffu, s, 8);
            s += __shfl_xor_sync(0xffffffffu, s, 4);
            s += __shfl_xor_sync(0xffffffffu, s, 2);
            s += __shfl_xor_sync(0xffffffffu, s, 1);
            if ((tid & 15) == 0) atomicAdd(&sb[(y0 & 3) * 4 + px], s);
        }
        __syncthreads();
        if (tid < 16) atomicAdd(&g_norm2[(b * 96 + ch) * 16 + tid], sb[tid]);
    }
}

// ---------------------------------------------------------------------------
// K3: gram via mma.sync bf16 split (hh + h*lo + lo*h)  [R8 version]
// ---------------------------------------------------------------------------
__global__ void __launch_bounds__(256, 2) k_gram_mma() {
    uint32_t* Qhi = (uint32_t*)dynsm;            // [96][36] u32
    uint32_t* Qlo = Qhi + 96 * 36;
    uint32_t* Khi = Qlo + 96 * 36;
    uint32_t* Klo = Khi + 96 * 36;

    int bh = blockIdx.y;
    int b = bh >> 3, h = bh & 7;
    int tid = threadIdx.x, wid = tid >> 5, lane = tid & 31;
    int gr = lane >> 2, lp = lane & 3;
    int mg = wid >> 2, ng = wid & 3;             // m base mg*48, n base ng*24

    const float* qb = g_dw + (b * NC3 + h * 6) * HW;
    const float* kb = qb + 48 * HW;

    float acc[3][3][4];
#pragma unroll
    for (int tm = 0; tm < 3; tm++)
#pragma unroll
        for (int tn = 0; tn < 3; tn++)
#pragma unroll
            for (int e = 0; e < 4; e++) acc[tm][tn][e] = 0.f;

    for (int sub = 0; sub < 8; sub++) {
        int n0 = blockIdx.x * 512 + sub * 64;
        int i = n0 >> 7, j0 = n0 & 127;

        for (int e = tid; e < 768; e += 256) {
            int rg = e >> 5, jp = e & 31;
            int cc = rg >> 2, nh = rg & 3;
            int off = cc * HW + (4 * i + nh) * 512 + 4 * (j0 + 2 * jp);
            float4 q0 = *(const float4*)(qb + off);
            float4 q1 = *(const float4*)(qb + off + 4);
            float4 k0 = *(const float4*)(kb + off);
            float4 k1 = *(const float4*)(kb + off + 4);
            int rb = rg * 4;
            uint32_t hi, lo;
            split2(q0.x, q1.x, hi, lo); Qhi[(rb+0)*36+jp] = hi; Qlo[(rb+0)*36+jp] = lo;
            split2(q0.y, q1.y, hi, lo); Qhi[(rb+1)*36+jp] = hi; Qlo[(rb+1)*36+jp] = lo;
            split2(q0.z, q1.z, hi, lo); Qhi[(rb+2)*36+jp] = hi; Qlo[(rb+2)*36+jp] = lo;
            split2(q0.w, q1.w, hi, lo); Qhi[(rb+3)*36+jp] = hi; Qlo[(rb+3)*36+jp] = lo;
            split2(k0.x, k1.x, hi, lo); Khi[(rb+0)*36+jp] = hi; Klo[(rb+0)*36+jp] = lo;
            split2(k0.y, k1.y, hi, lo); Khi[(rb+1)*36+jp] = hi; Klo[(rb+1)*36+jp] = lo;
            split2(k0.z, k1.z, hi, lo); Khi[(rb+2)*36+jp] = hi; Klo[(rb+2)*36+jp] = lo;
            split2(k0.w, k1.w, hi, lo); Khi[(rb+3)*36+jp] = hi; Klo[(rb+3)*36+jp] = lo;
        }
        __syncthreads();

#pragma unroll
        for (int kc = 0; kc < 4; kc++) {
            uint32_t ahi[3][4], alo[3][4], bhi[3][2], blo[3][2];
#pragma unroll
            for (int tm = 0; tm < 3; tm++) {
                int r0 = (mg * 48 + tm * 16 + gr) * 36 + kc * 8 + lp;
                int r1 = r0 + 8 * 36;
                ahi[tm][0] = Qhi[r0];     ahi[tm][1] = Qhi[r1];
                ahi[tm][2] = Qhi[r0 + 4]; ahi[tm][3] = Qhi[r1 + 4];
                alo[tm][0] = Qlo[r0];     alo[tm][1] = Qlo[r1];
                alo[tm][2] = Qlo[r0 + 4]; alo[tm][3] = Qlo[r1 + 4];
            }
#pragma unroll
            for (int tn = 0; tn < 3; tn++) {
                int rb = (ng * 24 + tn * 8 + gr) * 36 + kc * 8 + lp;
                bhi[tn][0] = Khi[rb]; bhi[tn][1] = Khi[rb + 4];
                blo[tn][0] = Klo[rb]; blo[tn][1] = Klo[rb + 4];
            }
#pragma unroll
            for (int tm = 0; tm < 3; tm++)
#pragma unroll
                for (int tn = 0; tn < 3; tn++) {
                    mma_bf16(acc[tm][tn], ahi[tm], bhi[tn][0], bhi[tn][1]);
                    mma_bf16(acc[tm][tn], ahi[tm], blo[tn][0], blo[tn][1]);
                    mma_bf16(acc[tm][tn], alo[tm], bhi[tn][0], bhi[tn][1]);
                }
        }
        __syncthreads();
    }

    float* Sp = g_S + bh * 9216;
#pragma unroll
    for (int tm = 0; tm < 3; tm++)
#pragma unroll
        for (int tn = 0; tn < 3; tn++) {
            int r0 = mg * 48 + tm * 16 + gr;
            int c0 = ng * 24 + tn * 8 + 2 * lp;
            atomicAdd(&Sp[r0 * 96 + c0],           acc[tm][tn][0]);
            atomicAdd(&Sp[r0 * 96 + c0 + 1],       acc[tm][tn][1]);
            atomicAdd(&Sp[(r0 + 8) * 96 + c0],     acc[tm][tn][2]);
            atomicAdd(&Sp[(r0 + 8) * 96 + c0 + 1], acc[tm][tn][3]);
        }
}

// ---------------------------------------------------------------------------
// K4: fold norms + temperature, softmax rows (in-place in g_S)
// ---------------------------------------------------------------------------
__global__ void k_soft(const float* __restrict__ temp) {
    int bh = blockIdx.x;
    int b = bh >> 3, h = bh & 7;
    int r = threadIdx.x;                     // 0..95
    __shared__ float nk[96];

    float sq = g_norm2[(b * 96 + h * 6 + (r >> 4)) * 16 + (r & 15)];
    float nq = fmaxf(sqrtf(sq), 1e-12f);
    float sk = g_norm2[(b * 96 + 48 + h * 6 + (r >> 4)) * 16 + (r & 15)];
    nk[r] = fmaxf(sqrtf(sk), 1e-12f);
    __syncthreads();

    float t = temp[h];
    float* row = g_S + (bh * 96 + r) * 96;
    float vals[96];
    float m = -1e30f;
#pragma unroll
    for (int d = 0; d < 96; d++) {
        float a = row[d] / (nq * nk[d]) * t;
        vals[d] = a;
        m = fmaxf(m, a);
    }
    float ssum = 0.f;
#pragma unroll
    for (int d = 0; d < 96; d++) {
        float e = expf(vals[d] - m);
        vals[d] = e;
        ssum += e;
    }
    float inv = 1.f / ssum;
#pragma unroll
    for (int d = 0; d < 96; d++) row[d] = vals[d] * inv;
}

// ---------------------------------------------------------------------------
// K5: attn @ V via mma.sync bf16 split.  A = attn[96 c][96 d] (natural),
// B = Vt[64 px][96 d] (transposed during fill). No atomics: k fully in-block.
// grid (32 px-chunks of 512, 16 bh); 8 warps = 2 m-groups(48c) x 4 n-groups(16px)
// ---------------------------------------------------------------------------
__global__ void __launch_bounds__(256, 2) k_av_mma() {
    uint32_t* Ahi = (uint32_t*)dynsm;            // [96][52] u32
    uint32_t* Alo = Ahi + 96 * 52;
    uint32_t* Vhi = Alo + 96 * 52;               // [64][49] u32
    uint32_t* Vlo = Vhi + 64 * 49;

    int bh = blockIdx.y;
    int b = bh >> 3, h = bh & 7;
    int tid = threadIdx.x, wid = tid >> 5, lane = tid & 31;
    int gr = lane >> 2, lp = lane & 3;
    int mg = wid >> 2, ng = wid & 3;

    // fill attn once: [c][d] bf16 hi/lo, pitch 52 u32
    const float* Sp = g_S + bh * 9216;
    for (int e = tid; e < 4608; e += 256) {
        int c = e / 48, dp = e - c * 48;
        float2 f = *(const float2*)(Sp + c * 96 + 2 * dp);
        uint32_t hi, lo;
        split2(f.x, f.y, hi, lo);
        Ahi[c * 52 + dp] = hi;
        Alo[c * 52 + dp] = lo;
    }

    const float* vb = g_dw + (b * NC3 + 96 + h * 6) * HW;
    float* ob = g_ao + (b * NCH + h * 6) * HW;

    for (int sub = 0; sub < 8; sub++) {
        int n0 = blockIdx.x * 512 + sub * 64;
        int i = n0 >> 7, j0 = n0 & 127;

        __syncthreads();
        // fill Vt: float4 over 4 consecutive d at pixel c -> 2 bf16x2 u32
        for (int e = tid; e < 1536; e += 256) {
            int rg = e >> 6, c = e & 63;
            int dc = rg >> 2, dh = rg & 3;
            float4 f = *(const float4*)(vb + dc * HW + (4 * i + dh) * 512 + 4 * (j0 + c));
            uint32_t h0, l0, h1, l1;
            split2(f.x, f.y, h0, l0);
            split2(f.z, f.w, h1, l1);
            Vhi[c * 49 + 2 * rg]     = h0;
            Vhi[c * 49 + 2 * rg + 1] = h1;
            Vlo[c * 49 + 2 * rg]     = l0;
            Vlo[c * 49 + 2 * rg + 1] = l1;
        }
        __syncthreads();

        float acc[3][2][4];
#pragma unroll
        for (int tm = 0; tm < 3; tm++)
#pragma unroll
            for (int tn = 0; tn < 2; tn++)
#pragma unroll
                for (int e = 0; e < 4; e++) acc[tm][tn][e] = 0.f;

#pragma unroll
        for (int kc = 0; kc < 6; kc++) {
            uint32_t ahi[3][4], alo[3][4], bhi[2][2], blo[2][2];
#pragma unroll
            for (int tm = 0; tm < 3; tm++) {
                int r0 = (mg * 48 + tm * 16 + gr) * 52 + kc * 8 + lp;
                int r1 = r0 + 8 * 52;
                ahi[tm][0] = Ahi[r0];     ahi[tm][1] = Ahi[r1];
                ahi[tm][2] = Ahi[r0 + 4]; ahi[tm][3] = Ahi[r1 + 4];
                alo[tm][0] = Alo[r0];     alo[tm][1] = Alo[r1];
                alo[tm][2] = Alo[r0 + 4]; alo[tm][3] = Alo[r1 + 4];
            }
#pragma unroll
            for (int tn = 0; tn < 2; tn++) {
                int rb = (ng * 16 + tn * 8 + gr) * 49 + kc * 8 + lp;
                bhi[tn][0] = Vhi[rb]; bhi[tn][1] = Vhi[rb + 4];
                blo[tn][0] = Vlo[rb]; blo[tn][1] = Vlo[rb + 4];
            }
#pragma unroll
            for (int tm = 0; tm < 3; tm++)
#pragma unroll
                for (int tn = 0; tn < 2; tn++) {
                    mma_bf16(acc[tm][tn], ahi[tm], bhi[tn][0], bhi[tn][1]);
                    mma_bf16(acc[tm][tn], ahi[tm], blo[tn][0], blo[tn][1]);
                    mma_bf16(acc[tm][tn], alo[tm], bhi[tn][0], bhi[tn][1]);
                }
        }

        // epilogue: rows r, r+8 -> from_blocks channel mapping; cols -> pixels
#pragma unroll
        for (int tm = 0; tm < 3; tm++)
#pragma unroll
            for (int tn = 0; tn < 2; tn++) {
                int j = j0 + ng * 16 + tn * 8 + 2 * lp;
#pragma unroll
                for (int half = 0; half < 2; half++) {
                    int r = mg * 48 + tm * 16 + gr + 8 * half;
                    int cc = r >> 4, nh = (r >> 2) & 3, nw = r & 3;
                    int base = cc * HW + (4 * i + nh) * 512 + nw;
                    ob[base + 4 * j]       = acc[tm][tn][2 * half];
                    ob[base + 4 * (j + 1)] = acc[tm][tn][2 * half + 1];
                }
            }
    }
}

// ---------------------------------------------------------------------------
// K6: 1x1 proj 48 -> 48 as tiled GEMM [R5 f32x2 version]
// ---------------------------------------------------------------------------
__global__ void __launch_bounds__(256, 2) k_proj(const float* __restrict__ w,
                                                 float* __restrict__ out) {
    __shared__ __align__(16) float Ws[NCH * NCH];     // 2304 floats
    __shared__ __align__(16) float Xs[NCH * 128];     // 6144 floats
    int tid = threadIdx.x;
    int ty = tid >> 4, tx = tid & 15;

    int b = blockIdx.x >> 11;
    int q = (blockIdx.x & 2047) * 128;
    const float* xb = g_ao + b * (NCH * HW) + q;

    for (int e = tid * 4; e < NCH * NCH; e += 1024)
        *(float4*)&Ws[e] = *(const float4*)&w[e];
    for (int e = tid; e < 1536; e += 256) {
        int ch = e >> 5, c = e & 31;
        *(float4*)&Xs[ch * 128 + 4 * c] = *(const float4*)&xb[ch * HW + 4 * c];
    }
    __syncthreads();

    u64 acc[3][4];
#pragma unroll
    for (int j = 0; j < 3; j++)
#pragma unroll
        for (int i = 0; i < 4; i++) acc[j][i] = 0;

#pragma unroll 4
    for (int k = 0; k < 48; k++) {
        ulonglong2 xa = *(const ulonglong2*)&Xs[k * 128 + 8 * tx];
        ulonglong2 xc = *(const ulonglong2*)&Xs[k * 128 + 8 * tx + 4];
#pragma unroll
        for (int j = 0; j < 3; j++) {
            float wf = Ws[(3 * ty + j) * 48 + k];
            u64 wp = pk2(wf, wf);
            fma2(acc[j][0], wp, xa.x);
            fma2(acc[j][1], wp, xa.y);
            fma2(acc[j][2], wp, xc.x);
            fma2(acc[j][3], wp, xc.y);
        }
    }

    float* op = out + b * (NCH * HW) + q + 8 * tx;
#pragma unroll
    for (int j = 0; j < 3; j++) {
        int oc = 3 * ty + j;
        float f0, f1, f2, f3, f4, f5, f6, f7;
        up2(acc[j][0], f0, f1);
        up2(acc[j][1], f2, f3);
        up2(acc[j][2], f4, f5);
        up2(acc[j][3], f6, f7);
        *(float4*)(op + oc * HW)     = make_float4(f0, f1, f2, f3);
        *(float4*)(op + oc * HW + 4) = make_float4(f4, f5, f6, f7);
    }
}

// ---------------------------------------------------------------------------
extern "C" void kernel_launch(void* const* d_in, const int* in_sizes, int n_in,
                              void* d_out, int out_size) {
    const float* x     = (const float*)d_in[0];
    const float* qkvw  = (const float*)d_in[1];
    const float* dww   = (const float*)d_in[2];
    const float* projw = (const float*)d_in[3];
    const float* temp  = (const float*)d_in[4];
    float* out = (float*)d_out;

    const int smem_gram = 4 * 96 * 36 * 4;                 // 55296
    const int smem_av   = (2 * 96 * 52 + 2 * 64 * 49) * 4; // 65024
    cudaFuncSetAttribute(k_qkv, cudaFuncAttributeMaxDynamicSharedMemorySize,
                         (6912 + 6144) * 4);
    cudaFuncSetAttribute(k_gram_mma, cudaFuncAttributeMaxDynamicSharedMemorySize,
                         smem_gram);
    cudaFuncSetAttribute(k_av_mma, cudaFuncAttributeMaxDynamicSharedMemorySize,
                         smem_av);

    k_zero<<<576, 256>>>();
    k_qkv<<<4096, 256, (6912 + 6144) * 4>>>(x, qkvw);
    k_dw<<<dim3(8, 64, NB_B * NC3), dim3(16, 8)>>>(dww);
    k_gram_mma<<<dim3(32, NB_B * NHEADS), 256, smem_gram>>>();
    k_soft<<<NB_B * NHEADS, 96>>>(temp);
    k_av_mma<<<dim3(32, NB_B * NHEADS), 256, smem_av>>>();
    k_proj<<<4096, 256>>>(projw, out);
}

// round 10
// speedup vs baseline: 1.5004x; 1.1519x over previous
#include <cuda_runtime.h>
#include <cuda_bf16.h>
#include <cstdint>

// Problem constants
#define HW     262144        // 512*512
#define NB_B   2
#define NCH    48
#define NC3    144
#define NHEADS 8

// Scratch (device globals: no allocation allowed)
__device__ float g_qkv[NB_B * NC3 * HW];     // after 1x1 qkv conv
__device__ float g_dw[NB_B * NC3 * HW];      // after depthwise 3x3
__device__ float g_ao[NB_B * NCH * HW];      // after attn@V (from_blocks layout)
__device__ float g_norm2[NB_B * 96 * 16];    // per (b, q/k-ch, y%4, x%4) sum sq
__device__ float g_S[NB_B * NHEADS * 96 * 96]; // gram -> softmaxed attn

typedef unsigned long long u64;

__device__ __forceinline__ void fma2(u64& d, u64 a, u64 b) {
    asm("fma.rn.f32x2 %0, %1, %2, %0;" : "+l"(d) : "l"(a), "l"(b));
}
__device__ __forceinline__ u64 pk2(float lo, float hi) {
    u64 r; asm("mov.b64 %0, {%1, %2};" : "=l"(r) : "f"(lo), "f"(hi)); return r;
}
__device__ __forceinline__ float hsum(u64 v) {
    float lo, hi; asm("mov.b64 {%0, %1}, %2;" : "=f"(lo), "=f"(hi) : "l"(v)); return lo + hi;
}
__device__ __forceinline__ void up2(u64 v, float& lo, float& hi) {
    asm("mov.b64 {%0, %1}, %2;" : "=f"(lo), "=f"(hi) : "l"(v));
}

// bf16 warp MMA: D[16x8] += A[16x16] row-major * B[8n x 16k] row-major
__device__ __forceinline__ void mma_bf16(float* d, const uint32_t* a,
                                         uint32_t b0, uint32_t b1) {
    asm volatile(
        "mma.sync.aligned.m16n8k16.row.col.f32.bf16.bf16.f32 "
        "{%0,%1,%2,%3}, {%4,%5,%6,%7}, {%8,%9}, {%0,%1,%2,%3};"
        : "+f"(d[0]), "+f"(d[1]), "+f"(d[2]), "+f"(d[3])
        : "r"(a[0]), "r"(a[1]), "r"(a[2]), "r"(a[3]), "r"(b0), "r"(b1));
}

// split v0,v1 into bf16 hi/lo pairs packed as u32 (low half = v0)
__device__ __forceinline__ void split2(float v0, float v1,
                                       uint32_t& hi, uint32_t& lo) {
    __nv_bfloat162 h = __floats2bfloat162_rn(v0, v1);
    float r0 = v0 - __bfloat162float(h.x);
    float r1 = v1 - __bfloat162float(h.y);
    __nv_bfloat162 l = __floats2bfloat162_rn(r0, r1);
    hi = *(uint32_t*)&h;
    lo = *(uint32_t*)&l;
}

extern __shared__ float dynsm[];

// ---------------------------------------------------------------------------
// K0: zero the accumulation buffers
// ---------------------------------------------------------------------------
__global__ void k_zero() {
    int i = blockIdx.x * 256 + threadIdx.x;
    if (i < NB_B * NHEADS * 96 * 96) g_S[i] = 0.f;
    if (i < NB_B * 96 * 16)          g_norm2[i] = 0.f;
}

// ---------------------------------------------------------------------------
// K1/K6: 1x1 conv via mma.sync, oc on m-axis, px on n-axis.
// Block: D[NOUT oc x 128 px] = W[NOUT x 48] @ X[48 x 128].  384 thr = 12 warps
// (3 mg x 4 ng). split-bf16 (hh + hl + lh). Epilogue: direct float2 stores.
// NOUT=144: mg covers 48 oc (3 m-tiles); NOUT=48: mg covers 16 oc (1 m-tile).
// ---------------------------------------------------------------------------
template<int NOUT>
__global__ void __launch_bounds__(384) k_c11_mma(const float* __restrict__ in,
                                                 const float* __restrict__ w,
                                                 float* __restrict__ out) {
    constexpr int MT = NOUT / 48;                 // m-tiles per warp (3 or 1)
    uint32_t* Whi = (uint32_t*)dynsm;             // [NOUT][28]
    uint32_t* Wlo = Whi + NOUT * 28;
    uint32_t* Xhi = Wlo + NOUT * 28;              // [128][28]
    uint32_t* Xlo = Xhi + 128 * 28;

    int tid = threadIdx.x, wid = tid >> 5, lane = tid & 31;
    int gr = lane >> 2, lp = lane & 3;
    int mg = wid >> 2, ng = wid & 3;              // m base mg*(MT*16), n base ng*32

    int b = blockIdx.x >> 11;
    int q0 = (blockIdx.x & 2047) * 128;
    const float* xb = in + b * (NCH * HW) + q0;

    // fill W: [oc][ic-pair] -> hi/lo u32
    for (int e = tid; e < NOUT * 24; e += 384) {
        int row = e / 24, kp = e - row * 24;
        float2 f = *(const float2*)(w + row * 48 + 2 * kp);
        uint32_t hi, lo;
        split2(f.x, f.y, hi, lo);
        Whi[row * 28 + kp] = hi;
        Wlo[row * 28 + kp] = lo;
    }
    // fill X: B[n=px][k=ic]; float4 over px at ic and ic+1 -> 4-row scatter
    for (int e = tid; e < 768; e += 384) {
        int icp = e >> 5, c = e & 31;
        float4 f0 = *(const float4*)(xb + (2 * icp) * HW + 4 * c);
        float4 f1 = *(const float4*)(xb + (2 * icp + 1) * HW + 4 * c);
        uint32_t hi, lo;
        split2(f0.x, f1.x, hi, lo); Xhi[(4*c+0)*28+icp] = hi; Xlo[(4*c+0)*28+icp] = lo;
        split2(f0.y, f1.y, hi, lo); Xhi[(4*c+1)*28+icp] = hi; Xlo[(4*c+1)*28+icp] = lo;
        split2(f0.z, f1.z, hi, lo); Xhi[(4*c+2)*28+icp] = hi; Xlo[(4*c+2)*28+icp] = lo;
        split2(f0.w, f1.w, hi, lo); Xhi[(4*c+3)*28+icp] = hi; Xlo[(4*c+3)*28+icp] = lo;
    }
    __syncthreads();

    float acc[MT][4][4];
#pragma unroll
    for (int tm = 0; tm < MT; tm++)
#pragma unroll
        for (int tn = 0; tn < 4; tn++)
#pragma unroll
            for (int e = 0; e < 4; e++) acc[tm][tn][e] = 0.f;

#pragma unroll
    for (int kc = 0; kc < 3; kc++) {
        uint32_t bhi[4][2], blo[4][2];
#pragma unroll
        for (int tn = 0; tn < 4; tn++) {
            int rb = (ng * 32 + tn * 8 + gr) * 28 + kc * 8 + lp;
            bhi[tn][0] = Xhi[rb]; bhi[tn][1] = Xhi[rb + 4];
            blo[tn][0] = Xlo[rb]; blo[tn][1] = Xlo[rb + 4];
        }
#pragma unroll
        for (int tm = 0; tm < MT; tm++) {
            int r0 = (mg * (MT * 16) + tm * 16 + gr) * 28 + kc * 8 + lp;
            int r1 = r0 + 8 * 28;
            uint32_t ahi[4], alo[4];
            ahi[0] = Whi[r0];     ahi[1] = Whi[r1];
            ahi[2] = Whi[r0 + 4]; ahi[3] = Whi[r1 + 4];
            alo[0] = Wlo[r0];     alo[1] = Wlo[r1];
            alo[2] = Wlo[r0 + 4]; alo[3] = Wlo[r1 + 4];
#pragma unroll
            for (int tn = 0; tn < 4; tn++) {
                mma_bf16(acc[tm][tn], ahi, bhi[tn][0], bhi[tn][1]);
                mma_bf16(acc[tm][tn], ahi, blo[tn][0], blo[tn][1]);
                mma_bf16(acc[tm][tn], alo, bhi[tn][0], bhi[tn][1]);
            }
        }
    }

    float* op = out + b * (NOUT * HW) + q0;
#pragma unroll
    for (int tm = 0; tm < MT; tm++)
#pragma unroll
        for (int tn = 0; tn < 4; tn++) {
            int col = ng * 32 + tn * 8 + 2 * lp;
            int r = mg * (MT * 16) + tm * 16 + gr;
            *(float2*)(op + r * HW + col)       = make_float2(acc[tm][tn][0], acc[tm][tn][1]);
            *(float2*)(op + (r + 8) * HW + col) = make_float2(acc[tm][tn][2], acc[tm][tn][3]);
        }
}

// ---------------------------------------------------------------------------
// K2: depthwise 3x3 (zero pad) + fused q/k squared-norm accumulation
// ---------------------------------------------------------------------------
__global__ void __launch_bounds__(128) k_dw(const float* __restrict__ dww) {
    int ch = blockIdx.z % NC3;
    int b  = blockIdx.z / NC3;
    __shared__ float wk[9];
    __shared__ float sb[16];
    int tid = threadIdx.y * 16 + threadIdx.x;
    if (tid < 9)  wk[tid] = dww[ch * 9 + tid];
    if (tid < 16) sb[tid] = 0.f;
    __syncthreads();

    int x0 = (blockIdx.x * 16 + threadIdx.x) * 4;
    int y0 = blockIdx.y * 8 + threadIdx.y;
    const float* in = g_qkv + (b * NC3 + ch) * HW;

    float v[3][6];
#pragma unroll
    for (int r = 0; r < 3; r++) {
        int y = y0 + r - 1;
        if (y >= 0 && y < 512) {
            const float* rp = in + y * 512;
            float4 m = *(const float4*)(rp + x0);
            v[r][0] = (x0 > 0) ? rp[x0 - 1] : 0.f;
            v[r][1] = m.x; v[r][2] = m.y; v[r][3] = m.z; v[r][4] = m.w;
            v[r][5] = (x0 + 4 < 512) ? rp[x0 + 4] : 0.f;
        } else {
#pragma unroll
            for (int c = 0; c < 6; c++) v[r][c] = 0.f;
        }
    }

    float o[4];
#pragma unroll
    for (int px = 0; px < 4; px++) {
        float s = 0.f;
#pragma unroll
        for (int r = 0; r < 3; r++)
#pragma unroll
            for (int c = 0; c < 3; c++)
                s += wk[r * 3 + c] * v[r][px + c];
        o[px] = s;
    }
    float4 ov = make_float4(o[0], o[1], o[2], o[3]);
    *(float4*)(g_dw + (b * NC3 + ch) * HW + y0 * 512 + x0) = ov;

    if (ch < 96) {
#pragma unroll
        for (int px = 0; px < 4; px++) {
            float s = o[px] * o[px];
            s += __shfl_xor_sync(0xffffffffu, s, 8);
            s += __shfl_xor_sync(0xffffffffu, s, 4);
            s += __shfl_xor_sync(0xffffffffu, s, 2);
            s += __shfl_xor_sync(0xffffffffu, s, 1);
            if ((tid & 15) == 0) atomicAdd(&sb[(y0 & 3) * 4 + px], s);
        }
        __syncthreads();
        if (tid < 16) atomicAdd(&g_norm2[(b * 96 + ch) * 16 + tid], sb[tid]);
    }
}

// ---------------------------------------------------------------------------
// K3: gram via mma.sync bf16 split (hh + h*lo + lo*h)  [R8 version]
// ---------------------------------------------------------------------------
__global__ void __launch_bounds__(256, 2) k_gram_mma() {
    uint32_t* Qhi = (uint32_t*)dynsm;            // [96][36] u32
    uint32_t* Qlo = Qhi + 96 * 36;
    uint32_t* Khi = Qlo + 96 * 36;
    uint32_t* Klo = Khi + 96 * 36;

    int bh = blockIdx.y;
    int b = bh >> 3, h = bh & 7;
    int tid = threadIdx.x, wid = tid >> 5, lane = tid & 31;
    int gr = lane >> 2, lp = lane & 3;
    int mg = wid >> 2, ng = wid & 3;             // m base mg*48, n base ng*24

    const float* qb = g_dw + (b * NC3 + h * 6) * HW;
    const float* kb = qb + 48 * HW;

    float acc[3][3][4];
#pragma unroll
    for (int tm = 0; tm < 3; tm++)
#pragma unroll
        for (int tn = 0; tn < 3; tn++)
#pragma unroll
            for (int e = 0; e < 4; e++) acc[tm][tn][e] = 0.f;

    for (int sub = 0; sub < 8; sub++) {
        int n0 = blockIdx.x * 512 + sub * 64;
        int i = n0 >> 7, j0 = n0 & 127;

        for (int e = tid; e < 768; e += 256) {
            int rg = e >> 5, jp = e & 31;
            int cc = rg >> 2, nh = rg & 3;
            int off = cc * HW + (4 * i + nh) * 512 + 4 * (j0 + 2 * jp);
            float4 q0 = *(const float4*)(qb + off);
            float4 q1 = *(const float4*)(qb + off + 4);
            float4 k0 = *(const float4*)(kb + off);
            float4 k1 = *(const float4*)(kb + off + 4);
            int rb = rg * 4;
            uint32_t hi, lo;
            split2(q0.x, q1.x, hi, lo); Qhi[(rb+0)*36+jp] = hi; Qlo[(rb+0)*36+jp] = lo;
            split2(q0.y, q1.y, hi, lo); Qhi[(rb+1)*36+jp] = hi; Qlo[(rb+1)*36+jp] = lo;
            split2(q0.z, q1.z, hi, lo); Qhi[(rb+2)*36+jp] = hi; Qlo[(rb+2)*36+jp] = lo;
            split2(q0.w, q1.w, hi, lo); Qhi[(rb+3)*36+jp] = hi; Qlo[(rb+3)*36+jp] = lo;
            split2(k0.x, k1.x, hi, lo); Khi[(rb+0)*36+jp] = hi; Klo[(rb+0)*36+jp] = lo;
            split2(k0.y, k1.y, hi, lo); Khi[(rb+1)*36+jp] = hi; Klo[(rb+1)*36+jp] = lo;
            split2(k0.z, k1.z, hi, lo); Khi[(rb+2)*36+jp] = hi; Klo[(rb+2)*36+jp] = lo;
            split2(k0.w, k1.w, hi, lo); Khi[(rb+3)*36+jp] = hi; Klo[(rb+3)*36+jp] = lo;
        }
        __syncthreads();

#pragma unroll
        for (int kc = 0; kc < 4; kc++) {
            uint32_t ahi[3][4], alo[3][4], bhi[3][2], blo[3][2];
#pragma unroll
            for (int tm = 0; tm < 3; tm++) {
                int r0 = (mg * 48 + tm * 16 + gr) * 36 + kc * 8 + lp;
                int r1 = r0 + 8 * 36;
                ahi[tm][0] = Qhi[r0];     ahi[tm][1] = Qhi[r1];
                ahi[tm][2] = Qhi[r0 + 4]; ahi[tm][3] = Qhi[r1 + 4];
                alo[tm][0] = Qlo[r0];     alo[tm][1] = Qlo[r1];
                alo[tm][2] = Qlo[r0 + 4]; alo[tm][3] = Qlo[r1 + 4];
            }
#pragma unroll
            for (int tn = 0; tn < 3; tn++) {
                int rb = (ng * 24 + tn * 8 + gr) * 36 + kc * 8 + lp;
                bhi[tn][0] = Khi[rb]; bhi[tn][1] = Khi[rb + 4];
                blo[tn][0] = Klo[rb]; blo[tn][1] = Klo[rb + 4];
            }
#pragma unroll
            for (int tm = 0; tm < 3; tm++)
#pragma unroll
                for (int tn = 0; tn < 3; tn++) {
                    mma_bf16(acc[tm][tn], ahi[tm], bhi[tn][0], bhi[tn][1]);
                    mma_bf16(acc[tm][tn], ahi[tm], blo[tn][0], blo[tn][1]);
                    mma_bf16(acc[tm][tn], alo[tm], bhi[tn][0], bhi[tn][1]);
                }
        }
        __syncthreads();
    }

    float* Sp = g_S + bh * 9216;
#pragma unroll
    for (int tm = 0; tm < 3; tm++)
#pragma unroll
        for (int tn = 0; tn < 3; tn++) {
            int r0 = mg * 48 + tm * 16 + gr;
            int c0 = ng * 24 + tn * 8 + 2 * lp;
            atomicAdd(&Sp[r0 * 96 + c0],           acc[tm][tn][0]);
            atomicAdd(&Sp[r0 * 96 + c0 + 1],       acc[tm][tn][1]);
            atomicAdd(&Sp[(r0 + 8) * 96 + c0],     acc[tm][tn][2]);
            atomicAdd(&Sp[(r0 + 8) * 96 + c0 + 1], acc[tm][tn][3]);
        }
}

// ---------------------------------------------------------------------------
// K4: fold norms + temperature, softmax rows (in-place in g_S)
// ---------------------------------------------------------------------------
__global__ void k_soft(const float* __restrict__ temp) {
    int bh = blockIdx.x;
    int b = bh >> 3, h = bh & 7;
    int r = threadIdx.x;                     // 0..95
    __shared__ float nk[96];

    float sq = g_norm2[(b * 96 + h * 6 + (r >> 4)) * 16 + (r & 15)];
    float nq = fmaxf(sqrtf(sq), 1e-12f);
    float sk = g_norm2[(b * 96 + 48 + h * 6 + (r >> 4)) * 16 + (r & 15)];
    nk[r] = fmaxf(sqrtf(sk), 1e-12f);
    __syncthreads();

    float t = temp[h];
    float* row = g_S + (bh * 96 + r) * 96;
    float vals[96];
    float m = -1e30f;
#pragma unroll
    for (int d = 0; d < 96; d++) {
        float a = row[d] / (nq * nk[d]) * t;
        vals[d] = a;
        m = fmaxf(m, a);
    }
    float ssum = 0.f;
#pragma unroll
    for (int d = 0; d < 96; d++) {
        float e = expf(vals[d] - m);
        vals[d] = e;
        ssum += e;
    }
    float inv = 1.f / ssum;
#pragma unroll
    for (int d = 0; d < 96; d++) row[d] = vals[d] * inv;
}

// ---------------------------------------------------------------------------
// K5: attn @ V via mma.sync bf16 split  [R9 version]
// ---------------------------------------------------------------------------
__global__ void __launch_bounds__(256, 2) k_av_mma() {
    uint32_t* Ahi = (uint32_t*)dynsm;            // [96][52] u32
    uint32_t* Alo = Ahi + 96 * 52;
    uint32_t* Vhi = Alo + 96 * 52;               // [64][49] u32
    uint32_t* Vlo = Vhi + 64 * 49;

    int bh = blockIdx.y;
    int b = bh >> 3, h = bh & 7;
    int tid = threadIdx.x, wid = tid >> 5, lane = tid & 31;
    int gr = lane >> 2, lp = lane & 3;
    int mg = wid >> 2, ng = wid & 3;

    const float* Sp = g_S + bh * 9216;
    for (int e = tid; e < 4608; e += 256) {
        int c = e / 48, dp = e - c * 48;
        float2 f = *(const float2*)(Sp + c * 96 + 2 * dp);
        uint32_t hi, lo;
        split2(f.x, f.y, hi, lo);
        Ahi[c * 52 + dp] = hi;
        Alo[c * 52 + dp] = lo;
    }

    const float* vb = g_dw + (b * NC3 + 96 + h * 6) * HW;
    float* ob = g_ao + (b * NCH + h * 6) * HW;

    for (int sub = 0; sub < 8; sub++) {
        int n0 = blockIdx.x * 512 + sub * 64;
        int i = n0 >> 7, j0 = n0 & 127;

        __syncthreads();
        for (int e = tid; e < 1536; e += 256) {
            int rg = e >> 6, c = e & 63;
            int dc = rg >> 2, dh = rg & 3;
            float4 f = *(const float4*)(vb + dc * HW + (4 * i + dh) * 512 + 4 * (j0 + c));
            uint32_t h0, l0, h1, l1;
            split2(f.x, f.y, h0, l0);
            split2(f.z, f.w, h1, l1);
            Vhi[c * 49 + 2 * rg]     = h0;
            Vhi[c * 49 + 2 * rg + 1] = h1;
            Vlo[c * 49 + 2 * rg]     = l0;
            Vlo[c * 49 + 2 * rg + 1] = l1;
        }
        __syncthreads();

        float acc[3][2][4];
#pragma unroll
        for (int tm = 0; tm < 3; tm++)
#pragma unroll
            for (int tn = 0; tn < 2; tn++)
#pragma unroll
                for (int e = 0; e < 4; e++) acc[tm][tn][e] = 0.f;

#pragma unroll
        for (int kc = 0; kc < 6; kc++) {
            uint32_t ahi[3][4], alo[3][4], bhi[2][2], blo[2][2];
#pragma unroll
            for (int tm = 0; tm < 3; tm++) {
                int r0 = (mg * 48 + tm * 16 + gr) * 52 + kc * 8 + lp;
                int r1 = r0 + 8 * 52;
                ahi[tm][0] = Ahi[r0];     ahi[tm][1] = Ahi[r1];
                ahi[tm][2] = Ahi[r0 + 4]; ahi[tm][3] = Ahi[r1 + 4];
                alo[tm][0] = Alo[r0];     alo[tm][1] = Alo[r1];
                alo[tm][2] = Alo[r0 + 4]; alo[tm][3] = Alo[r1 + 4];
            }
#pragma unroll
            for (int tn = 0; tn < 2; tn++) {
                int rb = (ng * 16 + tn * 8 + gr) * 49 + kc * 8 + lp;
                bhi[tn][0] = Vhi[rb]; bhi[tn][1] = Vhi[rb + 4];
                blo[tn][0] = Vlo[rb]; blo[tn][1] = Vlo[rb + 4];
            }
#pragma unroll
            for (int tm = 0; tm < 3; tm++)
#pragma unroll
                for (int tn = 0; tn < 2; tn++) {
                    mma_bf16(acc[tm][tn], ahi[tm], bhi[tn][0], bhi[tn][1]);
                    mma_bf16(acc[tm][tn], ahi[tm], blo[tn][0], blo[tn][1]);
                    mma_bf16(acc[tm][tn], alo[tm], bhi[tn][0], bhi[tn][1]);
                }
        }

#pragma unroll
        for (int tm = 0; tm < 3; tm++)
#pragma unroll
            for (int tn = 0; tn < 2; tn++) {
                int j = j0 + ng * 16 + tn * 8 + 2 * lp;
#pragma unroll
                for (int half = 0; half < 2; half++) {
                    int r = mg * 48 + tm * 16 + gr + 8 * half;
                    int cc = r >> 4, nh = (r >> 2) & 3, nw = r & 3;
                    int base = cc * HW + (4 * i + nh) * 512 + nw;
                    ob[base + 4 * j]       = acc[tm][tn][2 * half];
                    ob[base + 4 * (j + 1)] = acc[tm][tn][2 * half + 1];
                }
            }
    }
}

// ---------------------------------------------------------------------------
extern "C" void kernel_launch(void* const* d_in, const int* in_sizes, int n_in,
                              void* d_out, int out_size) {
    const float* x     = (const float*)d_in[0];
    const float* qkvw  = (const float*)d_in[1];
    const float* dww   = (const float*)d_in[2];
    const float* projw = (const float*)d_in[3];
    const float* temp  = (const float*)d_in[4];
    float* out = (float*)d_out;

    const int smem_qkv  = (144 * 28 * 2 + 128 * 28 * 2) * 4;  // 60928
    const int smem_proj = (48 * 28 * 2 + 128 * 28 * 2) * 4;   // 39424
    const int smem_gram = 4 * 96 * 36 * 4;                    // 55296
    const int smem_av   = (2 * 96 * 52 + 2 * 64 * 49) * 4;    // 65024
    cudaFuncSetAttribute(k_c11_mma<144>, cudaFuncAttributeMaxDynamicSharedMemorySize, smem_qkv);
    cudaFuncSetAttribute(k_c11_mma<48>,  cudaFuncAttributeMaxDynamicSharedMemorySize, smem_proj);
    cudaFuncSetAttribute(k_gram_mma, cudaFuncAttributeMaxDynamicSharedMemorySize, smem_gram);
    cudaFuncSetAttribute(k_av_mma,  cudaFuncAttributeMaxDynamicSharedMemorySize, smem_av);

    float* gqkv;  cudaGetSymbolAddress((void**)&gqkv, g_qkv);
    float* gao;   cudaGetSymbolAddress((void**)&gao,  g_ao);

    k_zero<<<576, 256>>>();
    k_c11_mma<144><<<4096, 384, smem_qkv>>>(x, qkvw, gqkv);
    k_dw<<<dim3(8, 64, NB_B * NC3), dim3(16, 8)>>>(dww);
    k_gram_mma<<<dim3(32, NB_B * NHEADS), 256, smem_gram>>>();
    k_soft<<<NB_B * NHEADS, 96>>>(temp);
    k_av_mma<<<dim3(32, NB_B * NHEADS), 256, smem_av>>>();
    k_c11_mma<48><<<4096, 384, smem_proj>>>(gao, projw, out);
}

// round 11
// speedup vs baseline: 1.7605x; 1.1734x over previous
#include <cuda_runtime.h>
#include <cuda_bf16.h>
#include <cstdint>

// Problem constants
#define HW     262144        // 512*512
#define NB_B   2
#define NCH    48
#define NC3    144
#define NHEADS 8

// Scratch (device globals: no allocation allowed)
__device__ float g_qkv[NB_B * NC3 * HW];     // after 1x1 qkv conv
__device__ float g_dw[NB_B * NC3 * HW];      // after depthwise 3x3
__device__ float g_ao[NB_B * NCH * HW];      // after attn@V (from_blocks layout)
__device__ float g_norm2[NB_B * 96 * 16];    // per (b, q/k-ch, y%4, x%4) sum sq
__device__ float g_S[NB_B * NHEADS * 96 * 96]; // gram -> softmaxed attn

typedef unsigned long long u64;

// bf16 warp MMA: D[16x8] += A[16x16] row-major * B[8n x 16k] row-major
__device__ __forceinline__ void mma_bf16(float* d, const uint32_t* a,
                                         uint32_t b0, uint32_t b1) {
    asm volatile(
        "mma.sync.aligned.m16n8k16.row.col.f32.bf16.bf16.f32 "
        "{%0,%1,%2,%3}, {%4,%5,%6,%7}, {%8,%9}, {%0,%1,%2,%3};"
        : "+f"(d[0]), "+f"(d[1]), "+f"(d[2]), "+f"(d[3])
        : "r"(a[0]), "r"(a[1]), "r"(a[2]), "r"(a[3]), "r"(b0), "r"(b1));
}

// split v0,v1 into bf16 hi/lo pairs packed as u32 (low half = v0)
__device__ __forceinline__ void split2(float v0, float v1,
                                       uint32_t& hi, uint32_t& lo) {
    __nv_bfloat162 h = __floats2bfloat162_rn(v0, v1);
    float r0 = v0 - __bfloat162float(h.x);
    float r1 = v1 - __bfloat162float(h.y);
    __nv_bfloat162 l = __floats2bfloat162_rn(r0, r1);
    hi = *(uint32_t*)&h;
    lo = *(uint32_t*)&l;
}

extern __shared__ float dynsm[];

// ---------------------------------------------------------------------------
// K0: zero the accumulation buffers
// ---------------------------------------------------------------------------
__global__ void k_zero() {
    int i = blockIdx.x * 256 + threadIdx.x;
    if (i < NB_B * NHEADS * 96 * 96) g_S[i] = 0.f;
    if (i < NB_B * 96 * 16)          g_norm2[i] = 0.f;
}

// ---------------------------------------------------------------------------
// K1/K6: 1x1 conv via mma.sync, oc on m-axis, px on n-axis  [R10 version]
// ---------------------------------------------------------------------------
template<int NOUT>
__global__ void __launch_bounds__(384) k_c11_mma(const float* __restrict__ in,
                                                 const float* __restrict__ w,
                                                 float* __restrict__ out) {
    constexpr int MT = NOUT / 48;                 // m-tiles per warp (3 or 1)
    uint32_t* Whi = (uint32_t*)dynsm;             // [NOUT][28]
    uint32_t* Wlo = Whi + NOUT * 28;
    uint32_t* Xhi = Wlo + NOUT * 28;              // [128][28]
    uint32_t* Xlo = Xhi + 128 * 28;

    int tid = threadIdx.x, wid = tid >> 5, lane = tid & 31;
    int gr = lane >> 2, lp = lane & 3;
    int mg = wid >> 2, ng = wid & 3;

    int b = blockIdx.x >> 11;
    int q0 = (blockIdx.x & 2047) * 128;
    const float* xb = in + b * (NCH * HW) + q0;

    for (int e = tid; e < NOUT * 24; e += 384) {
        int row = e / 24, kp = e - row * 24;
        float2 f = *(const float2*)(w + row * 48 + 2 * kp);
        uint32_t hi, lo;
        split2(f.x, f.y, hi, lo);
        Whi[row * 28 + kp] = hi;
        Wlo[row * 28 + kp] = lo;
    }
    for (int e = tid; e < 768; e += 384) {
        int icp = e >> 5, c = e & 31;
        float4 f0 = *(const float4*)(xb + (2 * icp) * HW + 4 * c);
        float4 f1 = *(const float4*)(xb + (2 * icp + 1) * HW + 4 * c);
        uint32_t hi, lo;
        split2(f0.x, f1.x, hi, lo); Xhi[(4*c+0)*28+icp] = hi; Xlo[(4*c+0)*28+icp] = lo;
        split2(f0.y, f1.y, hi, lo); Xhi[(4*c+1)*28+icp] = hi; Xlo[(4*c+1)*28+icp] = lo;
        split2(f0.z, f1.z, hi, lo); Xhi[(4*c+2)*28+icp] = hi; Xlo[(4*c+2)*28+icp] = lo;
        split2(f0.w, f1.w, hi, lo); Xhi[(4*c+3)*28+icp] = hi; Xlo[(4*c+3)*28+icp] = lo;
    }
    __syncthreads();

    float acc[MT][4][4];
#pragma unroll
    for (int tm = 0; tm < MT; tm++)
#pragma unroll
        for (int tn = 0; tn < 4; tn++)
#pragma unroll
            for (int e = 0; e < 4; e++) acc[tm][tn][e] = 0.f;

#pragma unroll
    for (int kc = 0; kc < 3; kc++) {
        uint32_t bhi[4][2], blo[4][2];
#pragma unroll
        for (int tn = 0; tn < 4; tn++) {
            int rb = (ng * 32 + tn * 8 + gr) * 28 + kc * 8 + lp;
            bhi[tn][0] = Xhi[rb]; bhi[tn][1] = Xhi[rb + 4];
            blo[tn][0] = Xlo[rb]; blo[tn][1] = Xlo[rb + 4];
        }
#pragma unroll
        for (int tm = 0; tm < MT; tm++) {
            int r0 = (mg * (MT * 16) + tm * 16 + gr) * 28 + kc * 8 + lp;
            int r1 = r0 + 8 * 28;
            uint32_t ahi[4], alo[4];
            ahi[0] = Whi[r0];     ahi[1] = Whi[r1];
            ahi[2] = Whi[r0 + 4]; ahi[3] = Whi[r1 + 4];
            alo[0] = Wlo[r0];     alo[1] = Wlo[r1];
            alo[2] = Wlo[r0 + 4]; alo[3] = Wlo[r1 + 4];
#pragma unroll
            for (int tn = 0; tn < 4; tn++) {
                mma_bf16(acc[tm][tn], ahi, bhi[tn][0], bhi[tn][1]);
                mma_bf16(acc[tm][tn], ahi, blo[tn][0], blo[tn][1]);
                mma_bf16(acc[tm][tn], alo, bhi[tn][0], bhi[tn][1]);
            }
        }
    }

    float* op = out + b * (NOUT * HW) + q0;
#pragma unroll
    for (int tm = 0; tm < MT; tm++)
#pragma unroll
        for (int tn = 0; tn < 4; tn++) {
            int col = ng * 32 + tn * 8 + 2 * lp;
            int r = mg * (MT * 16) + tm * 16 + gr;
            *(float2*)(op + r * HW + col)       = make_float2(acc[tm][tn][0], acc[tm][tn][1]);
            *(float2*)(op + (r + 8) * HW + col) = make_float2(acc[tm][tn][2], acc[tm][tn][3]);
        }
}

// ---------------------------------------------------------------------------
// K2: depthwise 3x3 (zero pad); 4 output rows per thread (vertical reuse)
// block (32,8); tile 128 px x 32 rows; grid (4, 16, 288). Norms moved to gram.
// ---------------------------------------------------------------------------
__global__ void __launch_bounds__(256) k_dw(const float* __restrict__ dww) {
    int ch = blockIdx.z % NC3;
    int b  = blockIdx.z / NC3;
    __shared__ float wk[9];
    int tid = threadIdx.y * 32 + threadIdx.x;
    if (tid < 9) wk[tid] = dww[ch * 9 + tid];
    __syncthreads();

    int x0 = (blockIdx.x * 32 + threadIdx.x) * 4;
    int y0 = blockIdx.y * 32 + threadIdx.y * 4;
    const float* in = g_qkv + (b * NC3 + ch) * HW;

    float v[6][6];
#pragma unroll
    for (int r = 0; r < 6; r++) {
        int y = y0 + r - 1;
        if (y >= 0 && y < 512) {
            const float* rp = in + y * 512;
            float4 m = *(const float4*)(rp + x0);
            v[r][0] = (x0 > 0) ? rp[x0 - 1] : 0.f;
            v[r][1] = m.x; v[r][2] = m.y; v[r][3] = m.z; v[r][4] = m.w;
            v[r][5] = (x0 + 4 < 512) ? rp[x0 + 4] : 0.f;
        } else {
#pragma unroll
            for (int c = 0; c < 6; c++) v[r][c] = 0.f;
        }
    }

    float* op = g_dw + (b * NC3 + ch) * HW;
#pragma unroll
    for (int orow = 0; orow < 4; orow++) {
        float o[4];
#pragma unroll
        for (int px = 0; px < 4; px++) {
            float s = 0.f;
#pragma unroll
            for (int dr = 0; dr < 3; dr++)
#pragma unroll
                for (int dc = 0; dc < 3; dc++)
                    s += wk[dr * 3 + dc] * v[orow + dr][px + dc];
            o[px] = s;
        }
        *(float4*)(op + (y0 + orow) * 512 + x0) = make_float4(o[0], o[1], o[2], o[3]);
    }
}

// ---------------------------------------------------------------------------
// K3: gram via mma.sync bf16 split + fused q/k norm accumulation in the fill
// (each (row,col) of q,k is touched exactly once across the fill loops)
// ---------------------------------------------------------------------------
__global__ void __launch_bounds__(256, 2) k_gram_mma() {
    uint32_t* Qhi = (uint32_t*)dynsm;            // [96][36] u32
    uint32_t* Qlo = Qhi + 96 * 36;
    uint32_t* Khi = Qlo + 96 * 36;
    uint32_t* Klo = Khi + 96 * 36;

    int bh = blockIdx.y;
    int b = bh >> 3, h = bh & 7;
    int tid = threadIdx.x, wid = tid >> 5, lane = tid & 31;
    int gr = lane >> 2, lp = lane & 3;
    int mg = wid >> 2, ng = wid & 3;             // m base mg*48, n base ng*24

    const float* qb = g_dw + (b * NC3 + h * 6) * HW;
    const float* kb = qb + 48 * HW;

    float acc[3][3][4];
#pragma unroll
    for (int tm = 0; tm < 3; tm++)
#pragma unroll
        for (int tn = 0; tn < 3; tn++)
#pragma unroll
            for (int e = 0; e < 4; e++) acc[tm][tn][e] = 0.f;

    float qn[3][4], kn[3][4];
#pragma unroll
    for (int ii = 0; ii < 3; ii++)
#pragma unroll
        for (int nw = 0; nw < 4; nw++) { qn[ii][nw] = 0.f; kn[ii][nw] = 0.f; }

    for (int sub = 0; sub < 8; sub++) {
        int n0 = blockIdx.x * 512 + sub * 64;
        int i = n0 >> 7, j0 = n0 & 127;

#pragma unroll
        for (int ii = 0; ii < 3; ii++) {
            int e = tid + (ii << 8);
            int rg = e >> 5, jp = e & 31;
            int cc = rg >> 2, nh = rg & 3;
            int off = cc * HW + (4 * i + nh) * 512 + 4 * (j0 + 2 * jp);
            float4 q0 = *(const float4*)(qb + off);
            float4 q1 = *(const float4*)(qb + off + 4);
            float4 k0 = *(const float4*)(kb + off);
            float4 k1 = *(const float4*)(kb + off + 4);
            int rb = rg * 4;
            uint32_t hi, lo;
            split2(q0.x, q1.x, hi, lo); Qhi[(rb+0)*36+jp] = hi; Qlo[(rb+0)*36+jp] = lo;
            split2(q0.y, q1.y, hi, lo); Qhi[(rb+1)*36+jp] = hi; Qlo[(rb+1)*36+jp] = lo;
            split2(q0.z, q1.z, hi, lo); Qhi[(rb+2)*36+jp] = hi; Qlo[(rb+2)*36+jp] = lo;
            split2(q0.w, q1.w, hi, lo); Qhi[(rb+3)*36+jp] = hi; Qlo[(rb+3)*36+jp] = lo;
            split2(k0.x, k1.x, hi, lo); Khi[(rb+0)*36+jp] = hi; Klo[(rb+0)*36+jp] = lo;
            split2(k0.y, k1.y, hi, lo); Khi[(rb+1)*36+jp] = hi; Klo[(rb+1)*36+jp] = lo;
            split2(k0.z, k1.z, hi, lo); Khi[(rb+2)*36+jp] = hi; Klo[(rb+2)*36+jp] = lo;
            split2(k0.w, k1.w, hi, lo); Khi[(rb+3)*36+jp] = hi; Klo[(rb+3)*36+jp] = lo;

            qn[ii][0] += q0.x * q0.x + q1.x * q1.x;
            qn[ii][1] += q0.y * q0.y + q1.y * q1.y;
            qn[ii][2] += q0.z * q0.z + q1.z * q1.z;
            qn[ii][3] += q0.w * q0.w + q1.w * q1.w;
            kn[ii][0] += k0.x * k0.x + k1.x * k1.x;
            kn[ii][1] += k0.y * k0.y + k1.y * k1.y;
            kn[ii][2] += k0.z * k0.z + k1.z * k1.z;
            kn[ii][3] += k0.w * k0.w + k1.w * k1.w;
        }
        __syncthreads();

#pragma unroll
        for (int kc = 0; kc < 4; kc++) {
            uint32_t ahi[3][4], alo[3][4], bhi[3][2], blo[3][2];
#pragma unroll
            for (int tm = 0; tm < 3; tm++) {
                int r0 = (mg * 48 + tm * 16 + gr) * 36 + kc * 8 + lp;
                int r1 = r0 + 8 * 36;
                ahi[tm][0] = Qhi[r0];     ahi[tm][1] = Qhi[r1];
                ahi[tm][2] = Qhi[r0 + 4]; ahi[tm][3] = Qhi[r1 + 4];
                alo[tm][0] = Qlo[r0];     alo[tm][1] = Qlo[r1];
                alo[tm][2] = Qlo[r0 + 4]; alo[tm][3] = Qlo[r1 + 4];
            }
#pragma unroll
            for (int tn = 0; tn < 3; tn++) {
                int rb = (ng * 24 + tn * 8 + gr) * 36 + kc * 8 + lp;
                bhi[tn][0] = Khi[rb]; bhi[tn][1] = Khi[rb + 4];
                blo[tn][0] = Klo[rb]; blo[tn][1] = Klo[rb + 4];
            }
#pragma unroll
            for (int tm = 0; tm < 3; tm++)
#pragma unroll
                for (int tn = 0; tn < 3; tn++) {
                    mma_bf16(acc[tm][tn], ahi[tm], bhi[tn][0], bhi[tn][1]);
                    mma_bf16(acc[tm][tn], ahi[tm], blo[tn][0], blo[tn][1]);
                    mma_bf16(acc[tm][tn], alo[tm], bhi[tn][0], bhi[tn][1]);
                }
        }
        __syncthreads();
    }

    // norm reduction: all lanes of a warp share the same row set
#pragma unroll
    for (int ii = 0; ii < 3; ii++)
#pragma unroll
        for (int nw = 0; nw < 4; nw++) {
            float sq = qn[ii][nw];
            float sk = kn[ii][nw];
            sq += __shfl_xor_sync(0xffffffffu, sq, 16);
            sk += __shfl_xor_sync(0xffffffffu, sk, 16);
            sq += __shfl_xor_sync(0xffffffffu, sq, 8);
            sk += __shfl_xor_sync(0xffffffffu, sk, 8);
            sq += __shfl_xor_sync(0xffffffffu, sq, 4);
            sk += __shfl_xor_sync(0xffffffffu, sk, 4);
            sq += __shfl_xor_sync(0xffffffffu, sq, 2);
            sk += __shfl_xor_sync(0xffffffffu, sk, 2);
            sq += __shfl_xor_sync(0xffffffffu, sq, 1);
            sk += __shfl_xor_sync(0xffffffffu, sk, 1);
            if (lane == 0) {
                int row = 4 * (wid + 8 * ii) + nw;
                int bucket = (row >> 4) * 16 + (row & 15);
                atomicAdd(&g_norm2[(b * 96 + h * 6) * 16 + bucket], sq);
                atomicAdd(&g_norm2[(b * 96 + 48 + h * 6) * 16 + bucket], sk);
            }
        }

    float* Sp = g_S + bh * 9216;
#pragma unroll
    for (int tm = 0; tm < 3; tm++)
#pragma unroll
        for (int tn = 0; tn < 3; tn++) {
            int r0 = mg * 48 + tm * 16 + gr;
            int c0 = ng * 24 + tn * 8 + 2 * lp;
            atomicAdd(&Sp[r0 * 96 + c0],           acc[tm][tn][0]);
            atomicAdd(&Sp[r0 * 96 + c0 + 1],       acc[tm][tn][1]);
            atomicAdd(&Sp[(r0 + 8) * 96 + c0],     acc[tm][tn][2]);
            atomicAdd(&Sp[(r0 + 8) * 96 + c0 + 1], acc[tm][tn][3]);
        }
}

// ---------------------------------------------------------------------------
// K4: fold norms + temperature, softmax rows (in-place in g_S)
// ---------------------------------------------------------------------------
__global__ void k_soft(const float* __restrict__ temp) {
    int bh = blockIdx.x;
    int b = bh >> 3, h = bh & 7;
    int r = threadIdx.x;                     // 0..95
    __shared__ float nk[96];

    float sq = g_norm2[(b * 96 + h * 6 + (r >> 4)) * 16 + (r & 15)];
    float nq = fmaxf(sqrtf(sq), 1e-12f);
    float sk = g_norm2[(b * 96 + 48 + h * 6 + (r >> 4)) * 16 + (r & 15)];
    nk[r] = fmaxf(sqrtf(sk), 1e-12f);
    __syncthreads();

    float t = temp[h];
    float* row = g_S + (bh * 96 + r) * 96;
    float vals[96];
    float m = -1e30f;
#pragma unroll
    for (int d = 0; d < 96; d++) {
        float a = row[d] / (nq * nk[d]) * t;
        vals[d] = a;
        m = fmaxf(m, a);
    }
    float ssum = 0.f;
#pragma unroll
    for (int d = 0; d < 96; d++) {
        float e = expf(vals[d] - m);
        vals[d] = e;
        ssum += e;
    }
    float inv = 1.f / ssum;
#pragma unroll
    for (int d = 0; d < 96; d++) row[d] = vals[d] * inv;
}

// ---------------------------------------------------------------------------
// K5: attn @ V via mma.sync bf16 split  [R9 version]
// ---------------------------------------------------------------------------
__global__ void __launch_bounds__(256, 2) k_av_mma() {
    uint32_t* Ahi = (uint32_t*)dynsm;            // [96][52] u32
    uint32_t* Alo = Ahi + 96 * 52;
    uint32_t* Vhi = Alo + 96 * 52;               // [64][49] u32
    uint32_t* Vlo = Vhi + 64 * 49;

    int bh = blockIdx.y;
    int b = bh >> 3, h = bh & 7;
    int tid = threadIdx.x, wid = tid >> 5, lane = tid & 31;
    int gr = lane >> 2, lp = lane & 3;
    int mg = wid >> 2, ng = wid & 3;

    const float* Sp = g_S + bh * 9216;
    for (int e = tid; e < 4608; e += 256) {
        int c = e / 48, dp = e - c * 48;
        float2 f = *(const float2*)(Sp + c * 96 + 2 * dp);
        uint32_t hi, lo;
        split2(f.x, f.y, hi, lo);
        Ahi[c * 52 + dp] = hi;
        Alo[c * 52 + dp] = lo;
    }

    const float* vb = g_dw + (b * NC3 + 96 + h * 6) * HW;
    float* ob = g_ao + (b * NCH + h * 6) * HW;

    for (int sub = 0; sub < 8; sub++) {
        int n0 = blockIdx.x * 512 + sub * 64;
        int i = n0 >> 7, j0 = n0 & 127;

        __syncthreads();
        for (int e = tid; e < 1536; e += 256) {
            int rg = e >> 6, c = e & 63;
            int dc = rg >> 2, dh = rg & 3;
            float4 f = *(const float4*)(vb + dc * HW + (4 * i + dh) * 512 + 4 * (j0 + c));
            uint32_t h0, l0, h1, l1;
            split2(f.x, f.y, h0, l0);
            split2(f.z, f.w, h1, l1);
            Vhi[c * 49 + 2 * rg]     = h0;
            Vhi[c * 49 + 2 * rg + 1] = h1;
            Vlo[c * 49 + 2 * rg]     = l0;
            Vlo[c * 49 + 2 * rg + 1] = l1;
        }
        __syncthreads();

        float acc[3][2][4];
#pragma unroll
        for (int tm = 0; tm < 3; tm++)
#pragma unroll
            for (int tn = 0; tn < 2; tn++)
#pragma unroll
                for (int e = 0; e < 4; e++) acc[tm][tn][e] = 0.f;

#pragma unroll
        for (int kc = 0; kc < 6; kc++) {
            uint32_t ahi[3][4], alo[3][4], bhi[2][2], blo[2][2];
#pragma unroll
            for (int tm = 0; tm < 3; tm++) {
                int r0 = (mg * 48 + tm * 16 + gr) * 52 + kc * 8 + lp;
                int r1 = r0 + 8 * 52;
                ahi[tm][0] = Ahi[r0];     ahi[tm][1] = Ahi[r1];
                ahi[tm][2] = Ahi[r0 + 4]; ahi[tm][3] = Ahi[r1 + 4];
                alo[tm][0] = Alo[r0];     alo[tm][1] = Alo[r1];
                alo[tm][2] = Alo[r0 + 4]; alo[tm][3] = Alo[r1 + 4];
            }
#pragma unroll
            for (int tn = 0; tn < 2; tn++) {
                int rb = (ng * 16 + tn * 8 + gr) * 49 + kc * 8 + lp;
                bhi[tn][0] = Vhi[rb]; bhi[tn][1] = Vhi[rb + 4];
                blo[tn][0] = Vlo[rb]; blo[tn][1] = Vlo[rb + 4];
            }
#pragma unroll
            for (int tm = 0; tm < 3; tm++)
#pragma unroll
                for (int tn = 0; tn < 2; tn++) {
                    mma_bf16(acc[tm][tn], ahi[tm], bhi[tn][0], bhi[tn][1]);
                    mma_bf16(acc[tm][tn], ahi[tm], blo[tn][0], blo[tn][1]);
                    mma_bf16(acc[tm][tn], alo[tm], bhi[tn][0], bhi[tn][1]);
                }
        }

#pragma unroll
        for (int tm = 0; tm < 3; tm++)
#pragma unroll
            for (int tn = 0; tn < 2; tn++) {
                int j = j0 + ng * 16 + tn * 8 + 2 * lp;
#pragma unroll
                for (int half = 0; half < 2; half++) {
                    int r = mg * 48 + tm * 16 + gr + 8 * half;
                    int cc = r >> 4, nh = (r >> 2) & 3, nw = r & 3;
                    int base = cc * HW + (4 * i + nh) * 512 + nw;
                    ob[base + 4 * j]       = acc[tm][tn][2 * half];
                    ob[base + 4 * (j + 1)] = acc[tm][tn][2 * half + 1];
                }
            }
    }
}

// ---------------------------------------------------------------------------
extern "C" void kernel_launch(void* const* d_in, const int* in_sizes, int n_in,
                              void* d_out, int out_size) {
    const float* x     = (const float*)d_in[0];
    const float* qkvw  = (const float*)d_in[1];
    const float* dww   = (const float*)d_in[2];
    const float* projw = (const float*)d_in[3];
    const float* temp  = (const float*)d_in[4];
    float* out = (float*)d_out;

    const int smem_qkv  = (144 * 28 * 2 + 128 * 28 * 2) * 4;  // 60928
    const int smem_proj = (48 * 28 * 2 + 128 * 28 * 2) * 4;   // 39424
    const int smem_gram = 4 * 96 * 36 * 4;                    // 55296
    const int smem_av   = (2 * 96 * 52 + 2 * 64 * 49) * 4;    // 65024
    cudaFuncSetAttribute(k_c11_mma<144>, cudaFuncAttributeMaxDynamicSharedMemorySize, smem_qkv);
    cudaFuncSetAttribute(k_c11_mma<48>,  cudaFuncAttributeMaxDynamicSharedMemorySize, smem_proj);
    cudaFuncSetAttribute(k_gram_mma, cudaFuncAttributeMaxDynamicSharedMemorySize, smem_gram);
    cudaFuncSetAttribute(k_av_mma,  cudaFuncAttributeMaxDynamicSharedMemorySize, smem_av);

    float* gqkv;  cudaGetSymbolAddress((void**)&gqkv, g_qkv);
    float* gao;   cudaGetSymbolAddress((void**)&gao,  g_ao);

    k_zero<<<576, 256>>>();
    k_c11_mma<144><<<4096, 384, smem_qkv>>>(x, qkvw, gqkv);
    k_dw<<<dim3(4, 16, NB_B * NC3), dim3(32, 8)>>>(dww);
    k_gram_mma<<<dim3(32, NB_B * NHEADS), 256, smem_gram>>>();
    k_soft<<<NB_B * NHEADS, 96>>>(temp);
    k_av_mma<<<dim3(32, NB_B * NHEADS), 256, smem_av>>>();
    k_c11_mma<48><<<4096, 384, smem_proj>>>(gao, projw, out);
}